// round 3
// baseline (speedup 1.0000x reference)
#include <cuda_runtime.h>
#include <math.h>

#define SN 1536        // sequence length
#define SD 512         // model dim
#define SH 4           // heads
#define SDH 128        // head dim
#define SBINS 100
#define SNI 5
#define SNL 3
#define QPW_LD 514     // D+2
#define ISQ 0.0883883476483184405f  // 1/sqrt(128)

// ---------------- static scratch (single big buffer) ----------------
// sizes in floats
#define SZ_X    (SN*SD)
#define SZ_QKV  (SN*3*SD)
#define SZ_S    (SH*SN*SN)
#define SZ_O1   (SN*SD)
#define SZ_AO   (SN*SD)
#define SZ_K2   (SN*SD)
#define SZ_BQP  (SN*SD)
#define SZ_QB   (SN*SD)
#define SZ_E    (SH*SN*SN)
#define SZ_HB   (SN*128)
#define SZ_H    (SNI*SN*128)
#define SZ_LG   (SNI*SN*200)
#define SZ_SOFF (SNI*SN)
#define SZ_EOFF (SNI*SN)
#define SZ_G    (SH*15*SN)
#define SZ_AL   (SH*SN)
#define SZ_BE   (SH*SN)
#define SZ_A    (SD)
#define SZ_B    (SD)
#define SZ_MISC (32)

#define OFF_X    0
#define OFF_QKV  (OFF_X + SZ_X)
#define OFF_S    (OFF_QKV + SZ_QKV)
#define OFF_O1   (OFF_S + SZ_S)
#define OFF_AO   (OFF_O1 + SZ_O1)
#define OFF_K2   (OFF_AO + SZ_AO)
#define OFF_BQP  (OFF_K2 + SZ_K2)
#define OFF_QB   (OFF_BQP + SZ_BQP)
#define OFF_E    (OFF_QB + SZ_QB)
#define OFF_HB   (OFF_E + SZ_E)
#define OFF_H    (OFF_HB + SZ_HB)
#define OFF_LG   (OFF_H + SZ_H)
#define OFF_SOFF (OFF_LG + SZ_LG)
#define OFF_EOFF (OFF_SOFF + SZ_SOFF)
#define OFF_G    (OFF_EOFF + SZ_EOFF)
#define OFF_AL   (OFF_G + SZ_G)
#define OFF_BE   (OFF_AL + SZ_AL)
#define OFF_A    (OFF_BE + SZ_BE)
#define OFF_B    (OFF_A + SZ_A)
#define OFF_MISC (OFF_B + SZ_B)
#define BUF_TOTAL (OFF_MISC + SZ_MISC)

__device__ float g_buf[BUF_TOTAL];

// misc layout: 0 tmin, 1 tmax, [2..6] start, [7..11] end, [12..16] ds, [17..21] de

// ---------------- kernels ----------------

__global__ void k_x(const float* __restrict__ ne, const float* __restrict__ tp,
                    const float* __restrict__ wt, const float* __restrict__ bt,
                    float* __restrict__ X) {
    int idx = blockIdx.x * 256 + threadIdx.x;
    if (idx < SN * SD) {
        int i = idx >> 9, d = idx & 511;
        X[idx] = ne[idx] + tp[i] * wt[d] + bt[d];
    }
}

// C[M,N] = scale * A(MxK) * B(NxK)^T + bias ; optional relu. Batched via z.
__global__ void gemm_nt(int M, int N, int K,
                        const float* __restrict__ A, int lda, long sA,
                        const float* __restrict__ B, int ldb, long sB,
                        const float* __restrict__ bias,
                        float* __restrict__ C, int ldc, long sC,
                        float scale, int act) {
    A += (long)blockIdx.z * sA;
    B += (long)blockIdx.z * sB;
    C += (long)blockIdx.z * sC;
    int brow = blockIdx.y * 128, bcol = blockIdx.x * 128;
    __shared__ float As[8][128];
    __shared__ float Bs[8][128];
    int tid = threadIdx.x;
    int tr = tid >> 4, tc = tid & 15;
    float acc[8][8];
#pragma unroll
    for (int i = 0; i < 8; i++)
#pragma unroll
        for (int j = 0; j < 8; j++) acc[i][j] = 0.f;
    int ar = tid >> 1, ac = (tid & 1) * 4;
    for (int k0 = 0; k0 < K; k0 += 8) {
#pragma unroll
        for (int i = 0; i < 4; i++) {
            int c = k0 + ac + i;
            int r = brow + ar;
            As[ac + i][ar] = (r < M && c < K) ? A[(long)r * lda + c] : 0.f;
            int r2 = bcol + ar;
            Bs[ac + i][ar] = (r2 < N && c < K) ? B[(long)r2 * ldb + c] : 0.f;
        }
        __syncthreads();
#pragma unroll
        for (int kk = 0; kk < 8; kk++) {
            float ra[8], rb[8];
#pragma unroll
            for (int i = 0; i < 8; i++) ra[i] = As[kk][tr * 8 + i];
#pragma unroll
            for (int j = 0; j < 8; j++) rb[j] = Bs[kk][tc * 8 + j];
#pragma unroll
            for (int i = 0; i < 8; i++)
#pragma unroll
                for (int j = 0; j < 8; j++) acc[i][j] += ra[i] * rb[j];
        }
        __syncthreads();
    }
#pragma unroll
    for (int i = 0; i < 8; i++) {
        int r = brow + tr * 8 + i;
        if (r >= M) continue;
#pragma unroll
        for (int j = 0; j < 8; j++) {
            int c = bcol + tc * 8 + j;
            if (c < N) {
                float v = scale * acc[i][j];
                if (bias) v += bias[c];
                if (act) v = fmaxf(v, 0.f);
                C[(long)r * ldc + c] = v;
            }
        }
    }
}

// C[M,N] = A(MxK) * B(KxN). Batched via z.
__global__ void gemm_nn(int M, int N, int K,
                        const float* __restrict__ A, int lda, long sA,
                        const float* __restrict__ B, int ldb, long sB,
                        float* __restrict__ C, int ldc, long sC) {
    A += (long)blockIdx.z * sA;
    B += (long)blockIdx.z * sB;
    C += (long)blockIdx.z * sC;
    int brow = blockIdx.y * 128, bcol = blockIdx.x * 128;
    __shared__ float As[8][128];
    __shared__ float Bs[8][128];
    int tid = threadIdx.x;
    int tr = tid >> 4, tc = tid & 15;
    float acc[8][8];
#pragma unroll
    for (int i = 0; i < 8; i++)
#pragma unroll
        for (int j = 0; j < 8; j++) acc[i][j] = 0.f;
    int ar = tid >> 1, ac = (tid & 1) * 4;
    int bRow = tid >> 5, bCol = (tid & 31) * 4;
    for (int k0 = 0; k0 < K; k0 += 8) {
#pragma unroll
        for (int i = 0; i < 4; i++) {
            int c = k0 + ac + i;
            int r = brow + ar;
            As[ac + i][ar] = (r < M && c < K) ? A[(long)r * lda + c] : 0.f;
        }
#pragma unroll
        for (int i = 0; i < 4; i++) {
            int kr = k0 + bRow;
            int cc = bcol + bCol + i;
            Bs[bRow][bCol + i] = (kr < K && cc < N) ? B[(long)kr * ldb + cc] : 0.f;
        }
        __syncthreads();
#pragma unroll
        for (int kk = 0; kk < 8; kk++) {
            float ra[8], rb[8];
#pragma unroll
            for (int i = 0; i < 8; i++) ra[i] = As[kk][tr * 8 + i];
#pragma unroll
            for (int j = 0; j < 8; j++) rb[j] = Bs[kk][tc * 8 + j];
#pragma unroll
            for (int i = 0; i < 8; i++)
#pragma unroll
                for (int j = 0; j < 8; j++) acc[i][j] += ra[i] * rb[j];
        }
        __syncthreads();
    }
#pragma unroll
    for (int i = 0; i < 8; i++) {
        int r = brow + tr * 8 + i;
        if (r >= M) continue;
#pragma unroll
        for (int j = 0; j < 8; j++) {
            int c = bcol + tc * 8 + j;
            if (c < N) C[(long)r * ldc + c] = acc[i][j];
        }
    }
}

// row-wise exp(x - rowmax), optionally normalized. In place. One block per row.
__global__ void k_rowsoft(float* __restrict__ base, int cols, int normalize) {
    float* row = base + (long)blockIdx.x * cols;
    __shared__ float red[256];
    int tid = threadIdx.x;
    float m = -1e30f;
    for (int k = tid; k < cols; k += 256) m = fmaxf(m, row[k]);
    red[tid] = m;
    __syncthreads();
    for (int s = 128; s > 0; s >>= 1) {
        if (tid < s) red[tid] = fmaxf(red[tid], red[tid + s]);
        __syncthreads();
    }
    m = red[0];
    __syncthreads();
    float sum = 0.f;
    for (int k = tid; k < cols; k += 256) {
        float e = __expf(row[k] - m);
        row[k] = e;
        sum += e;
    }
    if (normalize) {
        red[tid] = sum;
        __syncthreads();
        for (int s = 128; s > 0; s >>= 1) {
            if (tid < s) red[tid] += red[tid + s];
            __syncthreads();
        }
        float inv = 1.f / red[0];
        for (int k = tid; k < cols; k += 256) row[k] *= inv;
    }
}

// pooled mean + classifier -> interval mask into out[10..14]
__global__ void k_pool_cls(const float* __restrict__ AO,
                           const float* __restrict__ w1, const float* __restrict__ b1,
                           const float* __restrict__ w2, const float* __restrict__ b2,
                           float* __restrict__ out, int out_size) {
    __shared__ float pooled[SD];
    __shared__ float h1[128];
    __shared__ float lg[5];
    int tid = threadIdx.x;  // 512
    float s = 0.f;
    for (int i = 0; i < SN; i++) s += AO[(long)i * SD + tid];
    pooled[tid] = s * (1.f / SN);
    __syncthreads();
    if (tid < 128) {
        float r = b1[tid];
        const float* wr = w1 + (long)tid * SD;
        for (int d = 0; d < SD; d++) r += wr[d] * pooled[d];
        h1[tid] = fmaxf(r, 0.f);
    }
    __syncthreads();
    if (tid < 5) {
        float r = b2[tid];
        const float* wr = w2 + (long)tid * 128;
        for (int j = 0; j < 128; j++) r += wr[j] * h1[j];
        lg[tid] = r;
    }
    __syncthreads();
    if (tid == 0) {
        int arg = 0;
        float best = lg[0];
        for (int i = 1; i < 5; i++)
            if (lg[i] > best) { best = lg[i]; arg = i; }
        int num = arg + 1;
        if (out_size >= 15)
            for (int i = 0; i < 5; i++) out[10 + i] = (i < num) ? 1.f : 0.f;
    }
}

__global__ void k_tmm(const float* __restrict__ tp, float* __restrict__ misc) {
    __shared__ float mn[256], mx[256];
    int tid = threadIdx.x;
    float a = 1e30f, b = -1e30f;
    for (int i = tid; i < SN; i += 256) {
        float v = tp[i];
        a = fminf(a, v);
        b = fmaxf(b, v);
    }
    mn[tid] = a; mx[tid] = b;
    __syncthreads();
    for (int s = 128; s > 0; s >>= 1) {
        if (tid < s) {
            mn[tid] = fminf(mn[tid], mn[tid + s]);
            mx[tid] = fmaxf(mx[tid], mx[tid + s]);
        }
        __syncthreads();
    }
    if (tid == 0) {
        float tmin = mn[0], tmax = mx[0];
        misc[0] = tmin; misc[1] = tmax;
        float step = (tmax - tmin) / 5.f;
        for (int i = 0; i < 5; i++) {
            misc[2 + i] = tmin + i * step;
            misc[7 + i] = tmin + (i + 1) * step;
        }
    }
}

// a = wq @ u, b = wq @ v  (u,v = last two cols of qp_w)
__global__ void k_ab(const float* __restrict__ in_w, const float* __restrict__ qp_w,
                     float* __restrict__ a, float* __restrict__ b) {
    __shared__ float u[SD], v[SD];
    int tid = threadIdx.x;  // 512
    u[tid] = qp_w[(long)tid * QPW_LD + 512];
    v[tid] = qp_w[(long)tid * QPW_LD + 513];
    __syncthreads();
    float sa = 0.f, sb = 0.f;
    const float* wr = in_w + (long)tid * SD;
    for (int d = 0; d < SD; d++) {
        float w = wr[d];
        sa += w * u[d];
        sb += w * v[d];
    }
    a[tid] = sa; b[tid] = sb;
}

// alpha[h][k] = (a_h . K2_h[k]) / sqrt(DH), beta similarly
__global__ void k_alphabeta(const float* __restrict__ a, const float* __restrict__ b,
                            const float* __restrict__ K2,
                            float* __restrict__ alpha, float* __restrict__ beta) {
    int h = blockIdx.y;
    int k = blockIdx.x * 256 + threadIdx.x;
    __shared__ float a_s[SDH], b_s[SDH];
    if (threadIdx.x < SDH) {
        a_s[threadIdx.x] = a[h * SDH + threadIdx.x];
        b_s[threadIdx.x] = b[h * SDH + threadIdx.x];
    }
    __syncthreads();
    if (k >= SN) return;
    const float* kr = K2 + (long)k * SD + h * SDH;
    float sa = 0.f, sb = 0.f;
    for (int j = 0; j < SDH; j++) {
        float kv = kr[j];
        sa += kv * a_s[j];
        sb += kv * b_s[j];
    }
    alpha[h * SN + k] = sa * ISQ;
    beta[h * SN + k] = sb * ISQ;
}

// H[i][row][j] = relu(HB[row][j] + s_i*w1[l][j][512] + e_i*w1[l][j][513])
__global__ void k_hbuf(const float* __restrict__ HB, const float* __restrict__ ref_w1,
                       const float* __restrict__ misc, float* __restrict__ H, int l) {
    int idx = blockIdx.x * 256 + threadIdx.x;
    if (idx >= SNI * SN * 128) return;
    int i = idx / (SN * 128);
    int rem = idx - i * SN * 128;
    int j = rem & 127;
    float s = misc[2 + i], e = misc[7 + i];
    const float* w = ref_w1 + ((long)l * 128 + j) * QPW_LD;
    float v = HB[rem] + s * w[512] + e * w[513];
    H[idx] = fmaxf(v, 0.f);
}

// per (interval,row): softmax over each 100-logit half dotted with weight_params
__global__ void k_soff(const float* __restrict__ LG, const float* __restrict__ wp,
                       float* __restrict__ SOFF, float* __restrict__ EOFF) {
    int r = blockIdx.x;          // i*1536 + row
    int warp = threadIdx.x >> 5, lane = threadIdx.x & 31;
    const float* row = LG + (long)r * 200 + warp * 100;
    float m = -1e30f;
    for (int k = lane; k < 100; k += 32) m = fmaxf(m, row[k]);
    for (int o = 16; o > 0; o >>= 1) m = fmaxf(m, __shfl_xor_sync(0xffffffffu, m, o));
    float s = 0.f, d = 0.f;
    for (int k = lane; k < 100; k += 32) {
        float e = __expf(row[k] - m);
        s += e;
        d += e * wp[k];
    }
    for (int o = 16; o > 0; o >>= 1) {
        s += __shfl_xor_sync(0xffffffffu, s, o);
        d += __shfl_xor_sync(0xffffffffu, d, o);
    }
    if (lane == 0) {
        float val = d / s;
        if (warp == 0) SOFF[r] = val; else EOFF[r] = val;
    }
}

// per (head,interval): G[g, g*soff, g*eoff], g = exp(c - cmax). Also zero ds/de.
__global__ void k_gprep(const float* __restrict__ alpha, const float* __restrict__ beta,
                        const float* __restrict__ SOFF, const float* __restrict__ EOFF,
                        float* __restrict__ misc, float* __restrict__ G) {
    int bx = blockIdx.x;
    int h = bx / 5, i = bx % 5;
    int tid = threadIdx.x;
    float s = misc[2 + i], e = misc[7 + i];
    __shared__ float red[256];
    float m = -1e30f;
    for (int k = tid; k < SN; k += 256)
        m = fmaxf(m, s * alpha[h * SN + k] + e * beta[h * SN + k]);
    red[tid] = m;
    __syncthreads();
    for (int st = 128; st > 0; st >>= 1) {
        if (tid < st) red[tid] = fmaxf(red[tid], red[tid + st]);
        __syncthreads();
    }
    m = red[0];
    float* base = G + ((long)(h * 15 + i * 3)) * SN;
    for (int k = tid; k < SN; k += 256) {
        float g = __expf(s * alpha[h * SN + k] + e * beta[h * SN + k] - m);
        base[k] = g;
        base[SN + k] = g * SOFF[i * SN + k];
        base[2 * SN + k] = g * EOFF[i * SN + k];
    }
    if (bx == 0 && tid < 10) misc[12 + tid] = 0.f;
}

// one pass over E per layer: 15 weighted row-sums per query row, then ds/de atomics
__global__ void k_accum(const float* __restrict__ E, const float* __restrict__ G,
                        float* __restrict__ misc) {
    int h = blockIdx.y;
    int warp = threadIdx.x >> 5, lane = threadIdx.x & 31;
    int q = blockIdx.x * 16 + warp;
    __shared__ float Gs[15][256];
    const float* Gh = G + (long)h * 15 * SN;
    const float* Erow = E + (long)h * SN * SN + (long)q * SN;
    float acc[15];
#pragma unroll
    for (int c = 0; c < 15; c++) acc[c] = 0.f;
    for (int k0 = 0; k0 < SN; k0 += 256) {
        __syncthreads();
        for (int idx = threadIdx.x; idx < 15 * 256; idx += 512) {
            int c = idx >> 8, kk = idx & 255;
            Gs[c][kk] = Gh[c * SN + k0 + kk];
        }
        __syncthreads();
#pragma unroll
        for (int s = 0; s < 8; s++) {
            int kk = lane + 32 * s;
            float ev = Erow[k0 + kk];
#pragma unroll
            for (int c = 0; c < 15; c++) acc[c] += ev * Gs[c][kk];
        }
    }
#pragma unroll
    for (int c = 0; c < 15; c++)
        for (int o = 16; o > 0; o >>= 1)
            acc[c] += __shfl_xor_sync(0xffffffffu, acc[c], o);
    if (lane == 0) {
#pragma unroll
        for (int i = 0; i < 5; i++) {
            float inv = 0.25f / acc[3 * i];
            atomicAdd(&misc[12 + i], acc[3 * i + 1] * inv);
            atomicAdd(&misc[17 + i], acc[3 * i + 2] * inv);
        }
    }
}

__global__ void k_update(float* __restrict__ misc) {
    int t = threadIdx.x;
    if (t < 5) {
        misc[2 + t] += misc[12 + t];
        misc[7 + t] += misc[17 + t];
    }
}

__global__ void k_outb(const float* __restrict__ misc, float* __restrict__ out, int out_size) {
    int t = threadIdx.x;
    if (t < 5 && out_size >= 10) {
        out[2 * t] = misc[2 + t];
        out[2 * t + 1] = misc[7 + t];
    }
}

// ---------------- host ----------------
extern "C" void kernel_launch(void* const* d_in, const int* in_sizes, int n_in,
                              void* d_out, int out_size) {
    const float* ne     = (const float*)d_in[0];
    const float* tp     = (const float*)d_in[1];
    const float* W_time = (const float*)d_in[3];
    const float* b_time = (const float*)d_in[4];
    const float* in_w   = (const float*)d_in[5];
    const float* in_b   = (const float*)d_in[6];
    const float* out_w  = (const float*)d_in[7];
    const float* out_b  = (const float*)d_in[8];
    const float* ic_w1  = (const float*)d_in[9];
    const float* ic_b1  = (const float*)d_in[10];
    const float* ic_w2  = (const float*)d_in[11];
    const float* ic_b2  = (const float*)d_in[12];
    const float* ref_w1 = (const float*)d_in[13];
    const float* ref_b1 = (const float*)d_in[14];
    const float* ref_w2 = (const float*)d_in[15];
    const float* ref_b2 = (const float*)d_in[16];
    const float* wp     = (const float*)d_in[17];
    const float* qp_w   = (const float*)d_in[18];
    const float* qp_b   = (const float*)d_in[19];
    float* out = (float*)d_out;

    float* buf = nullptr;
    cudaGetSymbolAddress((void**)&buf, g_buf);
    float* X    = buf + OFF_X;
    float* QKV  = buf + OFF_QKV;
    float* S    = buf + OFF_S;
    float* O1   = buf + OFF_O1;
    float* AO   = buf + OFF_AO;
    float* K2   = buf + OFF_K2;
    float* BQP  = buf + OFF_BQP;
    float* QB   = buf + OFF_QB;
    float* E    = buf + OFF_E;
    float* HB   = buf + OFF_HB;
    float* Hbuf = buf + OFF_H;
    float* LG   = buf + OFF_LG;
    float* SOFF = buf + OFF_SOFF;
    float* EOFF = buf + OFF_EOFF;
    float* G    = buf + OFF_G;
    float* AL   = buf + OFF_AL;
    float* BE   = buf + OFF_BE;
    float* Avec = buf + OFF_A;
    float* Bvec = buf + OFF_B;
    float* misc = buf + OFF_MISC;

    // x = ne + t*W_time^T + b_time
    k_x<<<(SN * SD + 255) / 256, 256>>>(ne, tp, W_time, b_time, X);

    // QKV = X @ in_w^T + in_b  (1536 x 1536)
    gemm_nt<<<dim3(12, 12, 1), 256>>>(SN, 3 * SD, SD, X, SD, 0, in_w, SD, 0, in_b,
                                      QKV, 3 * SD, 0, 1.f, 0);

    // per-head scores S = Qh @ Kh^T / sqrt(DH)
    gemm_nt<<<dim3(12, 12, SH), 256>>>(SN, SN, SDH, QKV, 3 * SD, SDH,
                                       QKV + SD, 3 * SD, SDH, nullptr,
                                       S, SN, (long)SN * SN, ISQ, 0);
    // softmax rows
    k_rowsoft<<<SH * SN, 256>>>(S, SN, 1);
    // O1_h = S_h @ V_h
    gemm_nn<<<dim3(1, 12, SH), 256>>>(SN, SDH, SN, S, SN, (long)SN * SN,
                                      QKV + 2 * SD, 3 * SD, SDH,
                                      O1, SD, SDH);
    // AO = O1 @ out_w^T + out_b
    gemm_nt<<<dim3(4, 12, 1), 256>>>(SN, SD, SD, O1, SD, 0, out_w, SD, 0, out_b,
                                     AO, SD, 0, 1.f, 0);

    // classifier -> interval mask (out[10..14])
    k_pool_cls<<<1, 512>>>(AO, ic_w1, ic_b1, ic_w2, ic_b2, out, out_size);

    // time grid
    k_tmm<<<1, 256>>>(tp, misc);

    // K2 = AO @ wk^T + bk
    gemm_nt<<<dim3(4, 12, 1), 256>>>(SN, SD, SD, AO, SD, 0, in_w + (long)SD * SD, SD, 0,
                                     in_b + SD, K2, SD, 0, 1.f, 0);
    // BQP = AO @ qp_w[:, :512]^T + qp_b
    gemm_nt<<<dim3(4, 12, 1), 256>>>(SN, SD, SD, AO, SD, 0, qp_w, QPW_LD, 0, qp_b,
                                     BQP, SD, 0, 1.f, 0);
    // QB = BQP @ wq^T + bq
    gemm_nt<<<dim3(4, 12, 1), 256>>>(SN, SD, SD, BQP, SD, 0, in_w, SD, 0, in_b,
                                     QB, SD, 0, 1.f, 0);
    // E = exp(QBh @ K2h^T / sqrt(DH) - rowmax)
    gemm_nt<<<dim3(12, 12, SH), 256>>>(SN, SN, SDH, QB, SD, SDH, K2, SD, SDH, nullptr,
                                       E, SN, (long)SN * SN, ISQ, 0);
    k_rowsoft<<<SH * SN, 256>>>(E, SN, 0);

    // rank-2 score perturbation vectors
    k_ab<<<1, 512>>>(in_w, qp_w, Avec, Bvec);
    k_alphabeta<<<dim3(6, SH), 256>>>(Avec, Bvec, K2, AL, BE);

    for (int l = 0; l < SNL; l++) {
        // hbase = AO @ ref_w1_l[:, :512]^T + ref_b1_l   (no relu yet)
        gemm_nt<<<dim3(1, 12, 1), 256>>>(SN, 128, SD, AO, SD, 0,
                                         ref_w1 + (long)l * 128 * QPW_LD, QPW_LD, 0,
                                         ref_b1 + l * 128, HB, 128, 0, 1.f, 0);
        // per-interval relu(hbase + s*w1s + e*w1e)
        k_hbuf<<<(SNI * SN * 128 + 255) / 256, 256>>>(HB, ref_w1, misc, Hbuf, l);
        // logits = H @ ref_w2_l^T + ref_b2_l (batched over intervals)
        gemm_nt<<<dim3(2, 12, SNI), 256>>>(SN, 200, 128, Hbuf, 128, (long)SN * 128,
                                           ref_w2 + (long)l * 200 * 128, 128, 0,
                                           ref_b2 + l * 200, LG, 200, (long)SN * 200,
                                           1.f, 0);
        // s_off / e_off
        k_soff<<<SNI * SN, 64>>>(LG, wp, SOFF, EOFF);
        // per-(head,interval) g vectors (+ zero ds/de)
        k_gprep<<<SH * SNI, 256>>>(AL, BE, SOFF, EOFF, misc, G);
        // single pass over E: ds/de
        k_accum<<<dim3(SN / 16, SH), 512>>>(E, G, misc);
        // start += ds; end += de
        k_update<<<1, 32>>>(misc);
    }

    k_outb<<<1, 32>>>(misc, out, out_size);
}

// round 4
// speedup vs baseline: 1.5884x; 1.5884x over previous
#include <cuda_runtime.h>
#include <math.h>

#define SN 1536        // sequence length
#define SD 512         // model dim
#define SH 4           // heads
#define SDH 128        // head dim
#define SBINS 100
#define SNI 5
#define SNL 3
#define QPW_LD 514     // D+2
#define ISQ 0.0883883476483184405f  // 1/sqrt(128)

// ---------------- static scratch (single big buffer) ----------------
#define SZ_X    (SN*SD)
#define SZ_QKV  (SN*3*SD)
#define SZ_S    (SH*SN*SN)
#define SZ_O1   (SN*SD)
#define SZ_AO   (SN*SD)
#define SZ_K2   (SN*SD)
#define SZ_BQP  (SN*SD)
#define SZ_QB   (SN*SD)
#define SZ_E    (SH*SN*SN)
#define SZ_HB   (SN*128)
#define SZ_H    (SNI*SN*128)
#define SZ_LG   (SNI*SN*200)
#define SZ_SOFF (SNI*SN)
#define SZ_EOFF (SNI*SN)
#define SZ_G    (SH*15*SN)
#define SZ_AL   (SH*SN)
#define SZ_BE   (SH*SN)
#define SZ_A    (SD)
#define SZ_B    (SD)
#define SZ_POOL (SD)
#define SZ_MISC (32)

#define OFF_X    0
#define OFF_QKV  (OFF_X + SZ_X)
#define OFF_S    (OFF_QKV + SZ_QKV)
#define OFF_O1   (OFF_S + SZ_S)
#define OFF_AO   (OFF_O1 + SZ_O1)
#define OFF_K2   (OFF_AO + SZ_AO)
#define OFF_BQP  (OFF_K2 + SZ_K2)
#define OFF_QB   (OFF_BQP + SZ_BQP)
#define OFF_E    (OFF_QB + SZ_QB)
#define OFF_HB   (OFF_E + SZ_E)
#define OFF_H    (OFF_HB + SZ_HB)
#define OFF_LG   (OFF_H + SZ_H)
#define OFF_SOFF (OFF_LG + SZ_LG)
#define OFF_EOFF (OFF_SOFF + SZ_SOFF)
#define OFF_G    (OFF_EOFF + SZ_EOFF)
#define OFF_AL   (OFF_G + SZ_G)
#define OFF_BE   (OFF_AL + SZ_AL)
#define OFF_A    (OFF_BE + SZ_BE)
#define OFF_B    (OFF_A + SZ_A)
#define OFF_POOL (OFF_B + SZ_B)
#define OFF_MISC (OFF_POOL + SZ_POOL)
#define BUF_TOTAL (OFF_MISC + SZ_MISC)

__device__ float g_buf[BUF_TOTAL];

// misc layout: 0 tmin, 1 tmax, [2..6] start, [7..11] end, [12..16] ds, [17..21] de

// ---------------- elementwise / init ----------------

__global__ void k_x(const float* __restrict__ ne, const float* __restrict__ tp,
                    const float* __restrict__ wt, const float* __restrict__ bt,
                    float* __restrict__ X, float* __restrict__ pool) {
    int idx = blockIdx.x * 256 + threadIdx.x;
    if (idx < SN * SD) {
        int i = idx >> 9, d = idx & 511;
        X[idx] = ne[idx] + tp[i] * wt[d] + bt[d];
    }
    if (idx < SD) pool[idx] = 0.f;   // re-zero pooled accumulator every launch
}

// C (contiguous, ldc==N) initialized with bias (or 0) before split-K atomics
__global__ void k_init(const float* __restrict__ bias, float* __restrict__ C,
                       int N, int total) {
    int idx = blockIdx.x * 256 + threadIdx.x;
    if (idx < total) C[idx] = bias ? bias[idx % N] : 0.f;
}

// ---------------- GEMMs (128x128 tile, 8x8/thread, reg-prefetch double buffer,
//                  split-K via atomicAdd into pre-initialized C) ----------------

// C[M,N] (+)= scale * A(MxK) * B(NxK)^T ; ksplit==1 -> direct write (+bias)
__global__ void __launch_bounds__(256, 2)
gemm_nt(int M, int N, int K,
        const float* __restrict__ A, int lda, long sA,
        const float* __restrict__ B, int ldb, long sB,
        const float* __restrict__ bias,
        float* __restrict__ C, int ldc, long sC,
        float scale, int ksplit) {
    int batch = blockIdx.z / ksplit;
    int kz    = blockIdx.z % ksplit;
    int Kc    = K / ksplit;
    int kbeg  = kz * Kc, kend = kbeg + Kc;
    A += (long)batch * sA;
    B += (long)batch * sB;
    C += (long)batch * sC;
    int brow = blockIdx.y * 128, bcol = blockIdx.x * 128;
    __shared__ float As[8][128];
    __shared__ float Bs[8][128];
    int tid = threadIdx.x;
    int tr = tid >> 4, tc = tid & 15;
    int ar = tid >> 1, ac = (tid & 1) * 4;
    int rA = brow + ar, rB = bcol + ar;

    float acc[8][8];
#pragma unroll
    for (int i = 0; i < 8; i++)
#pragma unroll
        for (int j = 0; j < 8; j++) acc[i][j] = 0.f;

    float pa[4], pb[4];
#pragma unroll
    for (int i = 0; i < 4; i++) {
        int c = kbeg + ac + i;
        pa[i] = (rA < M && c < kend) ? A[(long)rA * lda + c] : 0.f;
        pb[i] = (rB < N && c < kend) ? B[(long)rB * ldb + c] : 0.f;
    }

    for (int k0 = kbeg; k0 < kend; k0 += 8) {
#pragma unroll
        for (int i = 0; i < 4; i++) { As[ac + i][ar] = pa[i]; Bs[ac + i][ar] = pb[i]; }
        __syncthreads();
        int kn = k0 + 8;
        if (kn < kend) {
#pragma unroll
            for (int i = 0; i < 4; i++) {
                int c = kn + ac + i;
                pa[i] = (rA < M && c < kend) ? A[(long)rA * lda + c] : 0.f;
                pb[i] = (rB < N && c < kend) ? B[(long)rB * ldb + c] : 0.f;
            }
        }
#pragma unroll
        for (int kk = 0; kk < 8; kk++) {
            float ra[8], rb[8];
#pragma unroll
            for (int i = 0; i < 8; i++) ra[i] = As[kk][tr * 8 + i];
#pragma unroll
            for (int j = 0; j < 8; j++) rb[j] = Bs[kk][tc * 8 + j];
#pragma unroll
            for (int i = 0; i < 8; i++)
#pragma unroll
                for (int j = 0; j < 8; j++) acc[i][j] += ra[i] * rb[j];
        }
        __syncthreads();
    }

#pragma unroll
    for (int i = 0; i < 8; i++) {
        int r = brow + tr * 8 + i;
        if (r >= M) continue;
#pragma unroll
        for (int j = 0; j < 8; j++) {
            int c = bcol + tc * 8 + j;
            if (c < N) {
                float v = scale * acc[i][j];
                if (ksplit == 1) {
                    if (bias) v += bias[c];
                    C[(long)r * ldc + c] = v;
                } else {
                    atomicAdd(&C[(long)r * ldc + c], v);
                }
            }
        }
    }
}

// C[M,N] (+)= A(MxK) * B(KxN)
__global__ void __launch_bounds__(256, 2)
gemm_nn(int M, int N, int K,
        const float* __restrict__ A, int lda, long sA,
        const float* __restrict__ B, int ldb, long sB,
        float* __restrict__ C, int ldc, long sC, int ksplit) {
    int batch = blockIdx.z / ksplit;
    int kz    = blockIdx.z % ksplit;
    int Kc    = K / ksplit;
    int kbeg  = kz * Kc, kend = kbeg + Kc;
    A += (long)batch * sA;
    B += (long)batch * sB;
    C += (long)batch * sC;
    int brow = blockIdx.y * 128, bcol = blockIdx.x * 128;
    __shared__ float As[8][128];
    __shared__ float Bs[8][128];
    int tid = threadIdx.x;
    int tr = tid >> 4, tc = tid & 15;
    int ar = tid >> 1, ac = (tid & 1) * 4;
    int bRow = tid >> 5, bCol = (tid & 31) * 4;
    int rA = brow + ar;

    float acc[8][8];
#pragma unroll
    for (int i = 0; i < 8; i++)
#pragma unroll
        for (int j = 0; j < 8; j++) acc[i][j] = 0.f;

    float pa[4], pb[4];
#pragma unroll
    for (int i = 0; i < 4; i++) {
        int c = kbeg + ac + i;
        pa[i] = (rA < M && c < kend) ? A[(long)rA * lda + c] : 0.f;
        int kr = kbeg + bRow, cc = bcol + bCol + i;
        pb[i] = (kr < kend && cc < N) ? B[(long)kr * ldb + cc] : 0.f;
    }

    for (int k0 = kbeg; k0 < kend; k0 += 8) {
#pragma unroll
        for (int i = 0; i < 4; i++) { As[ac + i][ar] = pa[i]; Bs[bRow][bCol + i] = pb[i]; }
        __syncthreads();
        int kn = k0 + 8;
        if (kn < kend) {
#pragma unroll
            for (int i = 0; i < 4; i++) {
                int c = kn + ac + i;
                pa[i] = (rA < M && c < kend) ? A[(long)rA * lda + c] : 0.f;
                int kr = kn + bRow, cc = bcol + bCol + i;
                pb[i] = (kr < kend && cc < N) ? B[(long)kr * ldb + cc] : 0.f;
            }
        }
#pragma unroll
        for (int kk = 0; kk < 8; kk++) {
            float ra[8], rb[8];
#pragma unroll
            for (int i = 0; i < 8; i++) ra[i] = As[kk][tr * 8 + i];
#pragma unroll
            for (int j = 0; j < 8; j++) rb[j] = Bs[kk][tc * 8 + j];
#pragma unroll
            for (int i = 0; i < 8; i++)
#pragma unroll
                for (int j = 0; j < 8; j++) acc[i][j] += ra[i] * rb[j];
        }
        __syncthreads();
    }

#pragma unroll
    for (int i = 0; i < 8; i++) {
        int r = brow + tr * 8 + i;
        if (r >= M) continue;
#pragma unroll
        for (int j = 0; j < 8; j++) {
            int c = bcol + tc * 8 + j;
            if (c < N) {
                if (ksplit == 1) C[(long)r * ldc + c] = acc[i][j];
                else atomicAdd(&C[(long)r * ldc + c], acc[i][j]);
            }
        }
    }
}

// ---------------- softmax / reductions ----------------

// row-wise exp(x - rowmax), optionally normalized. In place. One block per row.
__global__ void k_rowsoft(float* __restrict__ base, int cols, int normalize) {
    float4* row = (float4*)(base + (long)blockIdx.x * cols);
    int n4 = cols >> 2;
    __shared__ float red[256];
    int tid = threadIdx.x;
    float m = -1e30f;
    for (int k = tid; k < n4; k += 256) {
        float4 v = row[k];
        m = fmaxf(m, fmaxf(fmaxf(v.x, v.y), fmaxf(v.z, v.w)));
    }
    red[tid] = m;
    __syncthreads();
    for (int s = 128; s > 0; s >>= 1) {
        if (tid < s) red[tid] = fmaxf(red[tid], red[tid + s]);
        __syncthreads();
    }
    m = red[0];
    __syncthreads();
    float sum = 0.f;
    for (int k = tid; k < n4; k += 256) {
        float4 v = row[k];
        v.x = __expf(v.x - m); v.y = __expf(v.y - m);
        v.z = __expf(v.z - m); v.w = __expf(v.w - m);
        row[k] = v;
        sum += v.x + v.y + v.z + v.w;
    }
    if (normalize) {
        red[tid] = sum;
        __syncthreads();
        for (int s = 128; s > 0; s >>= 1) {
            if (tid < s) red[tid] += red[tid + s];
            __syncthreads();
        }
        float inv = 1.f / red[0];
        for (int k = tid; k < n4; k += 256) {
            float4 v = row[k];
            v.x *= inv; v.y *= inv; v.z *= inv; v.w *= inv;
            row[k] = v;
        }
    }
}

// pooled mean: grid 12 blocks x 512 threads, partial row sums -> atomic
__global__ void k_pool(const float* __restrict__ AO, float* __restrict__ pool) {
    int d = threadIdx.x;           // 512
    int r0 = blockIdx.x * 128;
    float s = 0.f;
    for (int r = 0; r < 128; r++) s += AO[(long)(r0 + r) * SD + d];
    atomicAdd(&pool[d], s);
}

// classifier on pooled -> interval mask into out[10..14]
__global__ void k_cls(const float* __restrict__ pool,
                      const float* __restrict__ w1, const float* __restrict__ b1,
                      const float* __restrict__ w2, const float* __restrict__ b2,
                      float* __restrict__ out, int out_size) {
    __shared__ float pv[SD];
    __shared__ float h1[128];
    __shared__ float lg[5];
    int tid = threadIdx.x;  // 128
    for (int i = tid; i < SD; i += 128) pv[i] = pool[i] * (1.f / SN);
    __syncthreads();
    {
        float r = b1[tid];
        const float* wr = w1 + (long)tid * SD;
        for (int d = 0; d < SD; d++) r += wr[d] * pv[d];
        h1[tid] = fmaxf(r, 0.f);
    }
    __syncthreads();
    if (tid < 5) {
        float r = b2[tid];
        const float* wr = w2 + (long)tid * 128;
        for (int j = 0; j < 128; j++) r += wr[j] * h1[j];
        lg[tid] = r;
    }
    __syncthreads();
    if (tid == 0) {
        int arg = 0;
        float best = lg[0];
        for (int i = 1; i < 5; i++)
            if (lg[i] > best) { best = lg[i]; arg = i; }
        int num = arg + 1;
        if (out_size >= 15)
            for (int i = 0; i < 5; i++) out[10 + i] = (i < num) ? 1.f : 0.f;
    }
}

__global__ void k_tmm(const float* __restrict__ tp, float* __restrict__ misc) {
    __shared__ float mn[256], mx[256];
    int tid = threadIdx.x;
    float a = 1e30f, b = -1e30f;
    for (int i = tid; i < SN; i += 256) {
        float v = tp[i];
        a = fminf(a, v);
        b = fmaxf(b, v);
    }
    mn[tid] = a; mx[tid] = b;
    __syncthreads();
    for (int s = 128; s > 0; s >>= 1) {
        if (tid < s) {
            mn[tid] = fminf(mn[tid], mn[tid + s]);
            mx[tid] = fmaxf(mx[tid], mx[tid + s]);
        }
        __syncthreads();
    }
    if (tid == 0) {
        float tmin = mn[0], tmax = mx[0];
        misc[0] = tmin; misc[1] = tmax;
        float step = (tmax - tmin) / 5.f;
        for (int i = 0; i < 5; i++) {
            misc[2 + i] = tmin + i * step;
            misc[7 + i] = tmin + (i + 1) * step;
        }
    }
}

// a = wq @ u, b = wq @ v  (u,v = last two cols of qp_w)
__global__ void k_ab(const float* __restrict__ in_w, const float* __restrict__ qp_w,
                     float* __restrict__ a, float* __restrict__ b) {
    __shared__ float u[SD], v[SD];
    int tid = threadIdx.x;  // 512
    u[tid] = qp_w[(long)tid * QPW_LD + 512];
    v[tid] = qp_w[(long)tid * QPW_LD + 513];
    __syncthreads();
    float sa = 0.f, sb = 0.f;
    const float* wr = in_w + (long)tid * SD;
    for (int d = 0; d < SD; d++) {
        float w = wr[d];
        sa += w * u[d];
        sb += w * v[d];
    }
    a[tid] = sa; b[tid] = sb;
}

// alpha[h][k] = (a_h . K2_h[k]) / sqrt(DH), beta similarly
__global__ void k_alphabeta(const float* __restrict__ a, const float* __restrict__ b,
                            const float* __restrict__ K2,
                            float* __restrict__ alpha, float* __restrict__ beta) {
    int h = blockIdx.y;
    int k = blockIdx.x * 256 + threadIdx.x;
    __shared__ float a_s[SDH], b_s[SDH];
    if (threadIdx.x < SDH) {
        a_s[threadIdx.x] = a[h * SDH + threadIdx.x];
        b_s[threadIdx.x] = b[h * SDH + threadIdx.x];
    }
    __syncthreads();
    if (k >= SN) return;
    const float* kr = K2 + (long)k * SD + h * SDH;
    float sa = 0.f, sb = 0.f;
    for (int j = 0; j < SDH; j++) {
        float kv = kr[j];
        sa += kv * a_s[j];
        sb += kv * b_s[j];
    }
    alpha[h * SN + k] = sa * ISQ;
    beta[h * SN + k] = sb * ISQ;
}

// H[i][row][j] = relu(HB[row][j] + s_i*w1[l][j][512] + e_i*w1[l][j][513])
__global__ void k_hbuf(const float* __restrict__ HB, const float* __restrict__ ref_w1,
                       const float* __restrict__ misc, float* __restrict__ H, int l) {
    int idx = blockIdx.x * 256 + threadIdx.x;
    if (idx >= SNI * SN * 128) return;
    int i = idx / (SN * 128);
    int rem = idx - i * SN * 128;
    int j = rem & 127;
    float s = misc[2 + i], e = misc[7 + i];
    const float* w = ref_w1 + ((long)l * 128 + j) * QPW_LD;
    float v = HB[rem] + s * w[512] + e * w[513];
    H[idx] = fmaxf(v, 0.f);
}

// per (interval,row): softmax over each 100-logit half dotted with weight_params
__global__ void k_soff(const float* __restrict__ LG, const float* __restrict__ wp,
                       float* __restrict__ SOFF, float* __restrict__ EOFF) {
    int r = blockIdx.x;          // i*1536 + row
    int warp = threadIdx.x >> 5, lane = threadIdx.x & 31;
    const float* row = LG + (long)r * 200 + warp * 100;
    float m = -1e30f;
    for (int k = lane; k < 100; k += 32) m = fmaxf(m, row[k]);
    for (int o = 16; o > 0; o >>= 1) m = fmaxf(m, __shfl_xor_sync(0xffffffffu, m, o));
    float s = 0.f, d = 0.f;
    for (int k = lane; k < 100; k += 32) {
        float e = __expf(row[k] - m);
        s += e;
        d += e * wp[k];
    }
    for (int o = 16; o > 0; o >>= 1) {
        s += __shfl_xor_sync(0xffffffffu, s, o);
        d += __shfl_xor_sync(0xffffffffu, d, o);
    }
    if (lane == 0) {
        float val = d / s;
        if (warp == 0) SOFF[r] = val; else EOFF[r] = val;
    }
}

// per (head,interval): G[g, g*soff, g*eoff], g = exp(c - cmax). Also zero ds/de.
__global__ void k_gprep(const float* __restrict__ alpha, const float* __restrict__ beta,
                        const float* __restrict__ SOFF, const float* __restrict__ EOFF,
                        float* __restrict__ misc, float* __restrict__ G) {
    int bx = blockIdx.x;
    int h = bx / 5, i = bx % 5;
    int tid = threadIdx.x;
    float s = misc[2 + i], e = misc[7 + i];
    __shared__ float red[256];
    float m = -1e30f;
    for (int k = tid; k < SN; k += 256)
        m = fmaxf(m, s * alpha[h * SN + k] + e * beta[h * SN + k]);
    red[tid] = m;
    __syncthreads();
    for (int st = 128; st > 0; st >>= 1) {
        if (tid < st) red[tid] = fmaxf(red[tid], red[tid + st]);
        __syncthreads();
    }
    m = red[0];
    float* base = G + ((long)(h * 15 + i * 3)) * SN;
    for (int k = tid; k < SN; k += 256) {
        float g = __expf(s * alpha[h * SN + k] + e * beta[h * SN + k] - m);
        base[k] = g;
        base[SN + k] = g * SOFF[i * SN + k];
        base[2 * SN + k] = g * EOFF[i * SN + k];
    }
    if (bx == 0 && tid < 10) misc[12 + tid] = 0.f;
}

// one pass over E per layer: 15 weighted row-sums per query row, then ds/de atomics
__global__ void k_accum(const float* __restrict__ E, const float* __restrict__ G,
                        float* __restrict__ misc) {
    int h = blockIdx.y;
    int warp = threadIdx.x >> 5, lane = threadIdx.x & 31;
    int q = blockIdx.x * 16 + warp;
    __shared__ float Gs[15][256];
    const float* Gh = G + (long)h * 15 * SN;
    const float* Erow = E + (long)h * SN * SN + (long)q * SN;
    float acc[15];
#pragma unroll
    for (int c = 0; c < 15; c++) acc[c] = 0.f;
    for (int k0 = 0; k0 < SN; k0 += 256) {
        __syncthreads();
        for (int idx = threadIdx.x; idx < 15 * 256; idx += 512) {
            int c = idx >> 8, kk = idx & 255;
            Gs[c][kk] = Gh[c * SN + k0 + kk];
        }
        __syncthreads();
#pragma unroll
        for (int s = 0; s < 8; s++) {
            int kk = lane + 32 * s;
            float ev = Erow[k0 + kk];
#pragma unroll
            for (int c = 0; c < 15; c++) acc[c] += ev * Gs[c][kk];
        }
    }
#pragma unroll
    for (int c = 0; c < 15; c++)
        for (int o = 16; o > 0; o >>= 1)
            acc[c] += __shfl_xor_sync(0xffffffffu, acc[c], o);
    if (lane == 0) {
#pragma unroll
        for (int i = 0; i < 5; i++) {
            float inv = 0.25f / acc[3 * i];
            atomicAdd(&misc[12 + i], acc[3 * i + 1] * inv);
            atomicAdd(&misc[17 + i], acc[3 * i + 2] * inv);
        }
    }
}

__global__ void k_update(float* __restrict__ misc) {
    int t = threadIdx.x;
    if (t < 5) {
        misc[2 + t] += misc[12 + t];
        misc[7 + t] += misc[17 + t];
    }
}

__global__ void k_outb(const float* __restrict__ misc, float* __restrict__ out, int out_size) {
    int t = threadIdx.x;
    if (t < 5 && out_size >= 10) {
        out[2 * t] = misc[2 + t];
        out[2 * t + 1] = misc[7 + t];
    }
}

// ---------------- host ----------------
extern "C" void kernel_launch(void* const* d_in, const int* in_sizes, int n_in,
                              void* d_out, int out_size) {
    const float* ne     = (const float*)d_in[0];
    const float* tp     = (const float*)d_in[1];
    const float* W_time = (const float*)d_in[3];
    const float* b_time = (const float*)d_in[4];
    const float* in_w   = (const float*)d_in[5];
    const float* in_b   = (const float*)d_in[6];
    const float* out_w  = (const float*)d_in[7];
    const float* out_b  = (const float*)d_in[8];
    const float* ic_w1  = (const float*)d_in[9];
    const float* ic_b1  = (const float*)d_in[10];
    const float* ic_w2  = (const float*)d_in[11];
    const float* ic_b2  = (const float*)d_in[12];
    const float* ref_w1 = (const float*)d_in[13];
    const float* ref_b1 = (const float*)d_in[14];
    const float* ref_w2 = (const float*)d_in[15];
    const float* ref_b2 = (const float*)d_in[16];
    const float* wp     = (const float*)d_in[17];
    const float* qp_w   = (const float*)d_in[18];
    const float* qp_b   = (const float*)d_in[19];
    float* out = (float*)d_out;

    float* buf = nullptr;
    cudaGetSymbolAddress((void**)&buf, g_buf);
    float* X    = buf + OFF_X;
    float* QKV  = buf + OFF_QKV;
    float* S    = buf + OFF_S;
    float* O1   = buf + OFF_O1;
    float* AO   = buf + OFF_AO;
    float* K2   = buf + OFF_K2;
    float* BQP  = buf + OFF_BQP;
    float* QB   = buf + OFF_QB;
    float* E    = buf + OFF_E;
    float* HB   = buf + OFF_HB;
    float* Hbuf = buf + OFF_H;
    float* LG   = buf + OFF_LG;
    float* SOFF = buf + OFF_SOFF;
    float* EOFF = buf + OFF_EOFF;
    float* G    = buf + OFF_G;
    float* AL   = buf + OFF_AL;
    float* BE   = buf + OFF_BE;
    float* Avec = buf + OFF_A;
    float* Bvec = buf + OFF_B;
    float* pool = buf + OFF_POOL;
    float* misc = buf + OFF_MISC;

    // x = ne + t*W_time^T + b_time ; zero pooled accumulator
    k_x<<<(SN * SD + 255) / 256, 256>>>(ne, tp, W_time, b_time, X, pool);

    // QKV = X @ in_w^T + in_b  (split-K 2)
    k_init<<<(SN * 3 * SD + 255) / 256, 256>>>(in_b, QKV, 3 * SD, SN * 3 * SD);
    gemm_nt<<<dim3(12, 12, 2), 256>>>(SN, 3 * SD, SD, X, SD, 0, in_w, SD, 0, nullptr,
                                      QKV, 3 * SD, 0, 1.f, 2);

    // per-head scores S = Qh @ Kh^T / sqrt(DH)
    gemm_nt<<<dim3(12, 12, SH), 256>>>(SN, SN, SDH, QKV, 3 * SD, SDH,
                                       QKV + SD, 3 * SD, SDH, nullptr,
                                       S, SN, (long)SN * SN, ISQ, 1);
    k_rowsoft<<<SH * SN, 256>>>(S, SN, 1);

    // O1_h = S_h @ V_h  (split-K 8)
    k_init<<<(SN * SD + 255) / 256, 256>>>(nullptr, O1, SD, SN * SD);
    gemm_nn<<<dim3(1, 12, SH * 8), 256>>>(SN, SDH, SN, S, SN, (long)SN * SN,
                                          QKV + 2 * SD, 3 * SD, SDH,
                                          O1, SD, SDH, 8);

    // AO = O1 @ out_w^T + out_b  (split-K 4)
    k_init<<<(SN * SD + 255) / 256, 256>>>(out_b, AO, SD, SN * SD);
    gemm_nt<<<dim3(4, 12, 4), 256>>>(SN, SD, SD, O1, SD, 0, out_w, SD, 0, nullptr,
                                     AO, SD, 0, 1.f, 4);

    // classifier -> interval mask (out[10..14])
    k_pool<<<12, 512>>>(AO, pool);
    k_cls<<<1, 128>>>(pool, ic_w1, ic_b1, ic_w2, ic_b2, out, out_size);

    // time grid
    k_tmm<<<1, 256>>>(tp, misc);

    // K2 = AO @ wk^T + bk  (split-K 4)
    k_init<<<(SN * SD + 255) / 256, 256>>>(in_b + SD, K2, SD, SN * SD);
    gemm_nt<<<dim3(4, 12, 4), 256>>>(SN, SD, SD, AO, SD, 0, in_w + (long)SD * SD, SD, 0,
                                     nullptr, K2, SD, 0, 1.f, 4);
    // BQP = AO @ qp_w[:, :512]^T + qp_b
    k_init<<<(SN * SD + 255) / 256, 256>>>(qp_b, BQP, SD, SN * SD);
    gemm_nt<<<dim3(4, 12, 4), 256>>>(SN, SD, SD, AO, SD, 0, qp_w, QPW_LD, 0, nullptr,
                                     BQP, SD, 0, 1.f, 4);
    // QB = BQP @ wq^T + bq
    k_init<<<(SN * SD + 255) / 256, 256>>>(in_b, QB, SD, SN * SD);
    gemm_nt<<<dim3(4, 12, 4), 256>>>(SN, SD, SD, BQP, SD, 0, in_w, SD, 0, nullptr,
                                     QB, SD, 0, 1.f, 4);
    // E = exp(QBh @ K2h^T / sqrt(DH) - rowmax)
    gemm_nt<<<dim3(12, 12, SH), 256>>>(SN, SN, SDH, QB, SD, SDH, K2, SD, SDH, nullptr,
                                       E, SN, (long)SN * SN, ISQ, 1);
    k_rowsoft<<<SH * SN, 256>>>(E, SN, 0);

    // rank-2 score perturbation vectors
    k_ab<<<1, 512>>>(in_w, qp_w, Avec, Bvec);
    k_alphabeta<<<dim3(6, SH), 256>>>(Avec, Bvec, K2, AL, BE);

    for (int l = 0; l < SNL; l++) {
        // hbase = AO @ ref_w1_l[:, :512]^T + ref_b1_l  (split-K 8, no relu)
        k_init<<<(SN * 128 + 255) / 256, 256>>>(ref_b1 + l * 128, HB, 128, SN * 128);
        gemm_nt<<<dim3(1, 12, 8), 256>>>(SN, 128, SD, AO, SD, 0,
                                         ref_w1 + (long)l * 128 * QPW_LD, QPW_LD, 0,
                                         nullptr, HB, 128, 0, 1.f, 8);
        // per-interval relu(hbase + s*w1s + e*w1e)
        k_hbuf<<<(SNI * SN * 128 + 255) / 256, 256>>>(HB, ref_w1, misc, Hbuf, l);
        // logits = H @ ref_w2_l^T + ref_b2_l  (batched over intervals, split-K 2)
        k_init<<<(SNI * SN * 200 + 255) / 256, 256>>>(ref_b2 + l * 200, LG, 200,
                                                      SNI * SN * 200);
        gemm_nt<<<dim3(2, 12, SNI * 2), 256>>>(SN, 200, 128, Hbuf, 128, (long)SN * 128,
                                               ref_w2 + (long)l * 200 * 128, 128, 0,
                                               nullptr, LG, 200, (long)SN * 200,
                                               1.f, 2);
        // s_off / e_off
        k_soff<<<SNI * SN, 64>>>(LG, wp, SOFF, EOFF);
        // per-(head,interval) g vectors (+ zero ds/de)
        k_gprep<<<SH * SNI, 256>>>(AL, BE, SOFF, EOFF, misc, G);
        // single pass over E: ds/de
        k_accum<<<dim3(SN / 16, SH), 512>>>(E, G, misc);
        // start += ds; end += de
        k_update<<<1, 32>>>(misc);
    }

    k_outb<<<1, 32>>>(misc, out, out_size);
}

// round 6
// speedup vs baseline: 2.7633x; 1.7397x over previous
#include <cuda_runtime.h>
#include <cuda_bf16.h>
#include <math.h>

#define SN 1536        // sequence length
#define SD 512         // model dim
#define SH 4           // heads
#define SDH 128        // head dim
#define SNI 5
#define SNL 3
#define QPW_LD 514     // D+2
#define ISQ 0.0883883476483184405f  // 1/sqrt(128)

typedef unsigned int u32;

// ---------------- static scratch ----------------
#define SZ_X    (SN*SD)
#define SZ_QKV  (SN*3*SD)
#define SZ_S    (SH*SN*SN)
#define SZ_O1   (SN*SD)
#define SZ_AO   (SN*SD)
#define SZ_K2   (SN*SD)
#define SZ_BQP  (SN*SD)
#define SZ_QB   (SN*SD)
#define SZ_E    (SH*SN*SN)
#define SZ_VT   (SH*SDH*SN)
#define SZ_RS   (SH*SN)
#define SZ_HB   (SN*128)
#define SZ_H    (SNI*SN*128)
#define SZ_LG   (SNI*SN*200)
#define SZ_SOFF (SNI*SN)
#define SZ_EOFF (SNI*SN)
#define SZ_G    (SH*15*SN)
#define SZ_AL   (SH*SN)
#define SZ_BE   (SH*SN)
#define SZ_A    (SD)
#define SZ_B    (SD)
#define SZ_POOL (SD)
#define SZ_MISC (32)

#define OFF_X    0
#define OFF_QKV  (OFF_X + SZ_X)
#define OFF_S    (OFF_QKV + SZ_QKV)
#define OFF_O1   (OFF_S + SZ_S)
#define OFF_AO   (OFF_O1 + SZ_O1)
#define OFF_K2   (OFF_AO + SZ_AO)
#define OFF_BQP  (OFF_K2 + SZ_K2)
#define OFF_QB   (OFF_BQP + SZ_BQP)
#define OFF_E    (OFF_QB + SZ_QB)
#define OFF_VT   (OFF_E + SZ_E)
#define OFF_RS   (OFF_VT + SZ_VT)
#define OFF_HB   (OFF_RS + SZ_RS)
#define OFF_H    (OFF_HB + SZ_HB)
#define OFF_LG   (OFF_H + SZ_H)
#define OFF_SOFF (OFF_LG + SZ_LG)
#define OFF_EOFF (OFF_SOFF + SZ_SOFF)
#define OFF_G    (OFF_EOFF + SZ_EOFF)
#define OFF_AL   (OFF_G + SZ_G)
#define OFF_BE   (OFF_AL + SZ_AL)
#define OFF_A    (OFF_BE + SZ_BE)
#define OFF_B    (OFF_A + SZ_A)
#define OFF_POOL (OFF_B + SZ_B)
#define OFF_MISC (OFF_POOL + SZ_POOL)
#define BUF_TOTAL (OFF_MISC + SZ_MISC)

__device__ float g_buf[BUF_TOTAL];

// misc: 0 tmin, 1 tmax, [2..6] start, [7..11] end, [12..16] ds, [17..21] de

// ---------------- MMA helpers ----------------
__device__ __forceinline__ u32 smem_u32(const void* p) {
    u32 a;
    asm("{ .reg .u64 t; cvta.to.shared.u64 t, %1; cvt.u32.u64 %0, t; }" : "=r"(a) : "l"(p));
    return a;
}
__device__ __forceinline__ void ldsm4(u32* r, u32 addr) {
    asm volatile("ldmatrix.sync.aligned.m8n8.x4.shared.b16 {%0,%1,%2,%3}, [%4];"
                 : "=r"(r[0]), "=r"(r[1]), "=r"(r[2]), "=r"(r[3]) : "r"(addr));
}
__device__ __forceinline__ void mma16816(float* c, const u32* a, const u32* b) {
    asm volatile(
        "mma.sync.aligned.m16n8k16.row.col.f32.bf16.bf16.f32 "
        "{%0,%1,%2,%3}, {%4,%5,%6,%7}, {%8,%9}, {%0,%1,%2,%3};"
        : "+f"(c[0]), "+f"(c[1]), "+f"(c[2]), "+f"(c[3])
        : "r"(a[0]), "r"(a[1]), "r"(a[2]), "r"(a[3]), "r"(b[0]), "r"(b[1]));
}

// pack fp32x4 -> hi/lo bf16x4 (uint2 each)
__device__ __forceinline__ void split4(float4 v, uint2& hi, uint2& lo) {
    __nv_bfloat16 h0 = __float2bfloat16_rn(v.x), h1 = __float2bfloat16_rn(v.y),
                  h2 = __float2bfloat16_rn(v.z), h3 = __float2bfloat16_rn(v.w);
    __nv_bfloat162 hp0 = __halves2bfloat162(h0, h1), hp1 = __halves2bfloat162(h2, h3);
    __nv_bfloat162 lp0 = __floats2bfloat162_rn(v.x - __bfloat162float(h0),
                                               v.y - __bfloat162float(h1));
    __nv_bfloat162 lp1 = __floats2bfloat162_rn(v.z - __bfloat162float(h2),
                                               v.w - __bfloat162float(h3));
    hi = make_uint2(*(u32*)&hp0, *(u32*)&hp1);
    lo = make_uint2(*(u32*)&lp0, *(u32*)&lp1);
}

// ---------------- tensor-core NT GEMM (HMMA bf16, 3-term split) ----------------
// C[M,N] = scale * rowscale[r] * A(MxK) @ B(NxK)^T (+ bias)
// ksplit>1: atomicAdd into pre-initialized C. M%128==0, K%(32*ksplit)==0.
// Tile: 128x64, BK=32, 8 warps of 32x32.
#define LDT 40   // smem row stride in halves (80B, conflict-free ldmatrix)
__global__ void __launch_bounds__(256)
tgemm(int M, int N, int K,
      const float* __restrict__ A, int lda, long sA,
      const float* __restrict__ B, int ldb, long sB,
      const float* __restrict__ bias,
      float* __restrict__ C, int ldc, long sC,
      float scale, int ksplit,
      const float* __restrict__ rs, long sRS, int alignB) {
    __shared__ __nv_bfloat16 sA_[2][128 * LDT];
    __shared__ __nv_bfloat16 sB_[2][64 * LDT];

    int batch = blockIdx.z / ksplit;
    int kz = blockIdx.z % ksplit;
    int Kc = K / ksplit;
    int kbeg = kz * Kc;
    A += (long)batch * sA;
    B += (long)batch * sB;
    C += (long)batch * sC;
    int brow = blockIdx.y * 128, bcol = blockIdx.x * 64;

    int tid = threadIdx.x;
    int wid = tid >> 5, lane = tid & 31;
    int wm = (wid & 3) * 32;        // warp m offset
    int wn = (wid >> 2) * 32;       // warp n offset

    u32 aBase[2] = { smem_u32(sA_[0]), smem_u32(sA_[1]) };
    u32 bBase[2] = { smem_u32(sB_[0]), smem_u32(sB_[1]) };

    // ldmatrix lane geometry
    int rowsel = (lane & 7) + ((lane >> 3) & 1) * 8;
    int ksel = (lane >> 4) * 8;

    float acc[2][4][4];
#pragma unroll
    for (int mi = 0; mi < 2; mi++)
#pragma unroll
        for (int ni = 0; ni < 4; ni++)
#pragma unroll
            for (int j = 0; j < 4; j++) acc[mi][ni][j] = 0.f;

    // prefetch first tile
    float4 pa[4], pb[2];
#pragma unroll
    for (int i = 0; i < 4; i++) {
        int idx = tid + i * 256;
        int row = idx >> 3, col = (idx & 7) * 4;
        pa[i] = *(const float4*)(A + (long)(brow + row) * lda + kbeg + col);
    }
#pragma unroll
    for (int i = 0; i < 2; i++) {
        int idx = tid + i * 256;
        int row = idx >> 3, col = (idx & 7) * 4;
        int rB = bcol + row;
        if (rB < N) {
            const float* bp = B + (long)rB * ldb + kbeg + col;
            pb[i] = alignB ? *(const float4*)bp
                           : make_float4(bp[0], bp[1], bp[2], bp[3]);
        } else pb[i] = make_float4(0.f, 0.f, 0.f, 0.f);
    }

    for (int kc = 0; kc < Kc; kc += 32) {
        // store tile to smem (hi/lo)
#pragma unroll
        for (int i = 0; i < 4; i++) {
            int idx = tid + i * 256;
            int row = idx >> 3, col = (idx & 7) * 4;
            uint2 hi, lo;
            split4(pa[i], hi, lo);
            *(uint2*)&sA_[0][row * LDT + col] = hi;
            *(uint2*)&sA_[1][row * LDT + col] = lo;
        }
#pragma unroll
        for (int i = 0; i < 2; i++) {
            int idx = tid + i * 256;
            int row = idx >> 3, col = (idx & 7) * 4;
            uint2 hi, lo;
            split4(pb[i], hi, lo);
            *(uint2*)&sB_[0][row * LDT + col] = hi;
            *(uint2*)&sB_[1][row * LDT + col] = lo;
        }
        __syncthreads();

        // prefetch next tile
        int kn = kbeg + kc + 32;
        if (kc + 32 < Kc) {
#pragma unroll
            for (int i = 0; i < 4; i++) {
                int idx = tid + i * 256;
                int row = idx >> 3, col = (idx & 7) * 4;
                pa[i] = *(const float4*)(A + (long)(brow + row) * lda + kn + col);
            }
#pragma unroll
            for (int i = 0; i < 2; i++) {
                int idx = tid + i * 256;
                int row = idx >> 3, col = (idx & 7) * 4;
                int rB = bcol + row;
                if (rB < N) {
                    const float* bp = B + (long)rB * ldb + kn + col;
                    pb[i] = alignB ? *(const float4*)bp
                                   : make_float4(bp[0], bp[1], bp[2], bp[3]);
                } else pb[i] = make_float4(0.f, 0.f, 0.f, 0.f);
            }
        }

        // compute: 2 k16 steps
#pragma unroll
        for (int ks = 0; ks < 32; ks += 16) {
            u32 ahi[2][4], alo[2][4], bhi[4][2], blo[4][2];
#pragma unroll
            for (int mi = 0; mi < 2; mi++) {
                u32 off = ((wm + mi * 16 + rowsel) * LDT + ks + ksel) * 2;
                ldsm4(ahi[mi], aBase[0] + off);
                ldsm4(alo[mi], aBase[1] + off);
            }
#pragma unroll
            for (int nj = 0; nj < 2; nj++) {
                u32 off = ((wn + nj * 16 + rowsel) * LDT + ks + ksel) * 2;
                u32 t0[4], t1[4];
                ldsm4(t0, bBase[0] + off);
                ldsm4(t1, bBase[1] + off);
                bhi[2 * nj][0] = t0[0]; bhi[2 * nj][1] = t0[2];
                bhi[2 * nj + 1][0] = t0[1]; bhi[2 * nj + 1][1] = t0[3];
                blo[2 * nj][0] = t1[0]; blo[2 * nj][1] = t1[2];
                blo[2 * nj + 1][0] = t1[1]; blo[2 * nj + 1][1] = t1[3];
            }
#pragma unroll
            for (int mi = 0; mi < 2; mi++)
#pragma unroll
                for (int ni = 0; ni < 4; ni++) {
                    mma16816(acc[mi][ni], ahi[mi], bhi[ni]);
                    mma16816(acc[mi][ni], ahi[mi], blo[ni]);
                    mma16816(acc[mi][ni], alo[mi], bhi[ni]);
                }
        }
        __syncthreads();
    }

    // epilogue
    int g = lane >> 2, t = lane & 3;
#pragma unroll
    for (int mi = 0; mi < 2; mi++) {
        int r0 = brow + wm + mi * 16 + g;
        int r1 = r0 + 8;
        float s0 = scale * (rs ? rs[sRS * batch + r0] : 1.f);
        float s1 = scale * (rs ? rs[sRS * batch + r1] : 1.f);
#pragma unroll
        for (int ni = 0; ni < 4; ni++) {
            int cc = bcol + wn + ni * 8 + 2 * t;
            float v00 = acc[mi][ni][0] * s0, v01 = acc[mi][ni][1] * s0;
            float v10 = acc[mi][ni][2] * s1, v11 = acc[mi][ni][3] * s1;
            if (ksplit == 1) {
                if (bias) {
                    if (cc < N) { v00 += bias[cc]; v10 += bias[cc]; }
                    if (cc + 1 < N) { v01 += bias[cc + 1]; v11 += bias[cc + 1]; }
                }
                if (cc < N) { C[(long)r0 * ldc + cc] = v00; C[(long)r1 * ldc + cc] = v10; }
                if (cc + 1 < N) { C[(long)r0 * ldc + cc + 1] = v01; C[(long)r1 * ldc + cc + 1] = v11; }
            } else {
                if (cc < N) {
                    atomicAdd(&C[(long)r0 * ldc + cc], v00);
                    atomicAdd(&C[(long)r1 * ldc + cc], v10);
                }
                if (cc + 1 < N) {
                    atomicAdd(&C[(long)r0 * ldc + cc + 1], v01);
                    atomicAdd(&C[(long)r1 * ldc + cc + 1], v11);
                }
            }
        }
    }
}

// ---------------- small kernels ----------------

__global__ void k_x(const float* __restrict__ ne, const float* __restrict__ tp,
                    const float* __restrict__ wt, const float* __restrict__ bt,
                    float* __restrict__ X, float* __restrict__ pool) {
    int idx = blockIdx.x * 256 + threadIdx.x;
    if (idx < SN * SD) {
        int i = idx >> 9, d = idx & 511;
        X[idx] = ne[idx] + tp[i] * wt[d] + bt[d];
    }
    if (idx < SD) pool[idx] = 0.f;
}

__global__ void k_init5(float* __restrict__ O1, float* __restrict__ AO,
                        float* __restrict__ K2, float* __restrict__ BQP,
                        float* __restrict__ QB,
                        const float* __restrict__ out_b, const float* __restrict__ in_b,
                        const float* __restrict__ qp_b) {
    int idx = blockIdx.x * 256 + threadIdx.x;
    if (idx < SN * SD) {
        int c = idx & 511;
        O1[idx] = 0.f;
        AO[idx] = out_b[c];
        K2[idx] = in_b[SD + c];
        BQP[idx] = qp_b[c];
        QB[idx] = in_b[c];
    }
}

__global__ void k_init(const float* __restrict__ bias, float* __restrict__ C,
                       int N, int total) {
    int idx = blockIdx.x * 256 + threadIdx.x;
    if (idx < total) C[idx] = bias ? bias[idx % N] : 0.f;
}

// V transpose: VT[h][n][k] = QKV[k][2*SD + h*128 + n]
__global__ void k_vt(const float* __restrict__ QKV, float* __restrict__ VT) {
    __shared__ float t[32][33];
    int h = blockIdx.z;
    int k0 = blockIdx.x * 32, n0 = blockIdx.y * 32;
    int x = threadIdx.x, y0 = threadIdx.y;  // (32, 8)
#pragma unroll
    for (int dy = 0; dy < 32; dy += 8) {
        int k = k0 + y0 + dy;
        t[y0 + dy][x] = QKV[(long)k * (3 * SD) + 2 * SD + h * SDH + n0 + x];
    }
    __syncthreads();
#pragma unroll
    for (int dy = 0; dy < 32; dy += 8) {
        int n = n0 + y0 + dy;
        VT[((long)h * SDH + n) * SN + k0 + x] = t[x][y0 + dy];
    }
}

// single-pass row exp(x - rowmax); optional inverse-rowsum output
__global__ void k_rowsoft2(float* __restrict__ base, float* __restrict__ rsinv) {
    __shared__ float4 cache[SN / 4];
    __shared__ float red[256];
    float4* row = (float4*)(base + (long)blockIdx.x * SN);
    int tid = threadIdx.x;
    float m = -1e30f;
    for (int k = tid; k < SN / 4; k += 256) {
        float4 v = row[k];
        cache[k] = v;
        m = fmaxf(m, fmaxf(fmaxf(v.x, v.y), fmaxf(v.z, v.w)));
    }
    red[tid] = m;
    __syncthreads();
    for (int s = 128; s > 0; s >>= 1) {
        if (tid < s) red[tid] = fmaxf(red[tid], red[tid + s]);
        __syncthreads();
    }
    m = red[0];
    __syncthreads();
    float sum = 0.f;
    for (int k = tid; k < SN / 4; k += 256) {
        float4 v = cache[k];
        v.x = __expf(v.x - m); v.y = __expf(v.y - m);
        v.z = __expf(v.z - m); v.w = __expf(v.w - m);
        row[k] = v;
        sum += v.x + v.y + v.z + v.w;
    }
    if (rsinv) {
        red[tid] = sum;
        __syncthreads();
        for (int s = 128; s > 0; s >>= 1) {
            if (tid < s) red[tid] += red[tid + s];
            __syncthreads();
        }
        if (tid == 0) rsinv[blockIdx.x] = 1.f / red[0];
    }
}

__global__ void k_pool(const float* __restrict__ AO, float* __restrict__ pool) {
    int d = threadIdx.x;  // 512
    int r0 = blockIdx.x * 128;
    float s = 0.f;
    for (int r = 0; r < 128; r++) s += AO[(long)(r0 + r) * SD + d];
    atomicAdd(&pool[d], s);
}

__global__ void k_cls(const float* __restrict__ pool,
                      const float* __restrict__ w1, const float* __restrict__ b1,
                      const float* __restrict__ w2, const float* __restrict__ b2,
                      float* __restrict__ out, int out_size) {
    __shared__ float pv[SD];
    __shared__ float h1[128];
    __shared__ float lg[5];
    int tid = threadIdx.x;  // 128
    for (int i = tid; i < SD; i += 128) pv[i] = pool[i] * (1.f / SN);
    __syncthreads();
    {
        float r = b1[tid];
        const float* wr = w1 + (long)tid * SD;
        for (int d = 0; d < SD; d++) r += wr[d] * pv[d];
        h1[tid] = fmaxf(r, 0.f);
    }
    __syncthreads();
    if (tid < 5) {
        float r = b2[tid];
        const float* wr = w2 + (long)tid * 128;
        for (int j = 0; j < 128; j++) r += wr[j] * h1[j];
        lg[tid] = r;
    }
    __syncthreads();
    if (tid == 0) {
        int arg = 0;
        float best = lg[0];
        for (int i = 1; i < 5; i++)
            if (lg[i] > best) { best = lg[i]; arg = i; }
        int num = arg + 1;
        if (out_size >= 15)
            for (int i = 0; i < 5; i++) out[10 + i] = (i < num) ? 1.f : 0.f;
    }
}

__global__ void k_tmm(const float* __restrict__ tp, float* __restrict__ misc) {
    __shared__ float mn[256], mx[256];
    int tid = threadIdx.x;
    float a = 1e30f, b = -1e30f;
    for (int i = tid; i < SN; i += 256) {
        float v = tp[i];
        a = fminf(a, v);
        b = fmaxf(b, v);
    }
    mn[tid] = a; mx[tid] = b;
    __syncthreads();
    for (int s = 128; s > 0; s >>= 1) {
        if (tid < s) {
            mn[tid] = fminf(mn[tid], mn[tid + s]);
            mx[tid] = fmaxf(mx[tid], mx[tid + s]);
        }
        __syncthreads();
    }
    if (tid == 0) {
        float tmin = mn[0], tmax = mx[0];
        misc[0] = tmin; misc[1] = tmax;
        float step = (tmax - tmin) / 5.f;
        for (int i = 0; i < 5; i++) {
            misc[2 + i] = tmin + i * step;
            misc[7 + i] = tmin + (i + 1) * step;
        }
    }
}

__global__ void k_ab(const float* __restrict__ in_w, const float* __restrict__ qp_w,
                     float* __restrict__ a, float* __restrict__ b) {
    __shared__ float u[SD], v[SD];
    int tid = threadIdx.x;  // 512
    u[tid] = qp_w[(long)tid * QPW_LD + 512];
    v[tid] = qp_w[(long)tid * QPW_LD + 513];
    __syncthreads();
    float sa = 0.f, sb = 0.f;
    const float* wr = in_w + (long)tid * SD;
    for (int d = 0; d < SD; d++) {
        float w = wr[d];
        sa += w * u[d];
        sb += w * v[d];
    }
    a[tid] = sa; b[tid] = sb;
}

__global__ void k_alphabeta(const float* __restrict__ a, const float* __restrict__ b,
                            const float* __restrict__ K2,
                            float* __restrict__ alpha, float* __restrict__ beta) {
    int h = blockIdx.y;
    int k = blockIdx.x * 256 + threadIdx.x;
    __shared__ float a_s[SDH], b_s[SDH];
    if (threadIdx.x < SDH) {
        a_s[threadIdx.x] = a[h * SDH + threadIdx.x];
        b_s[threadIdx.x] = b[h * SDH + threadIdx.x];
    }
    __syncthreads();
    if (k >= SN) return;
    const float* kr = K2 + (long)k * SD + h * SDH;
    float sa = 0.f, sb = 0.f;
    for (int j = 0; j < SDH; j++) {
        float kv = kr[j];
        sa += kv * a_s[j];
        sb += kv * b_s[j];
    }
    alpha[h * SN + k] = sa * ISQ;
    beta[h * SN + k] = sb * ISQ;
}

__global__ void k_hbuf(const float* __restrict__ HB, const float* __restrict__ ref_w1,
                       const float* __restrict__ misc, float* __restrict__ H, int l) {
    int idx = blockIdx.x * 256 + threadIdx.x;
    if (idx >= SNI * SN * 128) return;
    int i = idx / (SN * 128);
    int rem = idx - i * SN * 128;
    int j = rem & 127;
    float s = misc[2 + i], e = misc[7 + i];
    const float* w = ref_w1 + ((long)l * 128 + j) * QPW_LD;
    float v = HB[rem] + s * w[512] + e * w[513];
    H[idx] = fmaxf(v, 0.f);
}

__global__ void k_soff(const float* __restrict__ LG, const float* __restrict__ wp,
                       float* __restrict__ SOFF, float* __restrict__ EOFF) {
    int r = blockIdx.x;
    int warp = threadIdx.x >> 5, lane = threadIdx.x & 31;
    const float* row = LG + (long)r * 200 + warp * 100;
    float m = -1e30f;
    for (int k = lane; k < 100; k += 32) m = fmaxf(m, row[k]);
    for (int o = 16; o > 0; o >>= 1) m = fmaxf(m, __shfl_xor_sync(0xffffffffu, m, o));
    float s = 0.f, d = 0.f;
    for (int k = lane; k < 100; k += 32) {
        float e = __expf(row[k] - m);
        s += e;
        d += e * wp[k];
    }
    for (int o = 16; o > 0; o >>= 1) {
        s += __shfl_xor_sync(0xffffffffu, s, o);
        d += __shfl_xor_sync(0xffffffffu, d, o);
    }
    if (lane == 0) {
        float val = d / s;
        if (warp == 0) SOFF[r] = val; else EOFF[r] = val;
    }
}

__global__ void k_gprep(const float* __restrict__ alpha, const float* __restrict__ beta,
                        const float* __restrict__ SOFF, const float* __restrict__ EOFF,
                        float* __restrict__ misc, float* __restrict__ G) {
    int bx = blockIdx.x;
    int h = bx / 5, i = bx % 5;
    int tid = threadIdx.x;
    float s = misc[2 + i], e = misc[7 + i];
    __shared__ float red[256];
    float m = -1e30f;
    for (int k = tid; k < SN; k += 256)
        m = fmaxf(m, s * alpha[h * SN + k] + e * beta[h * SN + k]);
    red[tid] = m;
    __syncthreads();
    for (int st = 128; st > 0; st >>= 1) {
        if (tid < st) red[tid] = fmaxf(red[tid], red[tid + st]);
        __syncthreads();
    }
    m = red[0];
    float* base = G + ((long)(h * 15 + i * 3)) * SN;
    for (int k = tid; k < SN; k += 256) {
        float g = __expf(s * alpha[h * SN + k] + e * beta[h * SN + k] - m);
        base[k] = g;
        base[SN + k] = g * SOFF[i * SN + k];
        base[2 * SN + k] = g * EOFF[i * SN + k];
    }
    if (bx == 0 && tid < 10) misc[12 + tid] = 0.f;
}

__global__ void k_accum(const float* __restrict__ E, const float* __restrict__ G,
                        float* __restrict__ misc) {
    int h = blockIdx.y;
    int warp = threadIdx.x >> 5, lane = threadIdx.x & 31;
    int q = blockIdx.x * 16 + warp;
    __shared__ float Gs[15][256];
    const float* Gh = G + (long)h * 15 * SN;
    const float* Erow = E + (long)h * SN * SN + (long)q * SN;
    float acc[15];
#pragma unroll
    for (int c = 0; c < 15; c++) acc[c] = 0.f;
    for (int k0 = 0; k0 < SN; k0 += 256) {
        __syncthreads();
        for (int idx = threadIdx.x; idx < 15 * 256; idx += 512) {
            int c = idx >> 8, kk = idx & 255;
            Gs[c][kk] = Gh[c * SN + k0 + kk];
        }
        __syncthreads();
#pragma unroll
        for (int s = 0; s < 8; s++) {
            int kk = lane + 32 * s;
            float ev = Erow[k0 + kk];
#pragma unroll
            for (int c = 0; c < 15; c++) acc[c] += ev * Gs[c][kk];
        }
    }
#pragma unroll
    for (int c = 0; c < 15; c++)
        for (int o = 16; o > 0; o >>= 1)
            acc[c] += __shfl_xor_sync(0xffffffffu, acc[c], o);
    if (lane == 0) {
#pragma unroll
        for (int i = 0; i < 5; i++) {
            float inv = 0.25f / acc[3 * i];
            atomicAdd(&misc[12 + i], acc[3 * i + 1] * inv);
            atomicAdd(&misc[17 + i], acc[3 * i + 2] * inv);
        }
    }
}

__global__ void k_update(float* __restrict__ misc) {
    int t = threadIdx.x;
    if (t < 5) {
        misc[2 + t] += misc[12 + t];
        misc[7 + t] += misc[17 + t];
    }
}

__global__ void k_outb(const float* __restrict__ misc, float* __restrict__ out, int out_size) {
    int t = threadIdx.x;
    if (t < 5 && out_size >= 10) {
        out[2 * t] = misc[2 + t];
        out[2 * t + 1] = misc[7 + t];
    }
}

// ---------------- host ----------------
extern "C" void kernel_launch(void* const* d_in, const int* in_sizes, int n_in,
                              void* d_out, int out_size) {
    const float* ne     = (const float*)d_in[0];
    const float* tp     = (const float*)d_in[1];
    const float* W_time = (const float*)d_in[3];
    const float* b_time = (const float*)d_in[4];
    const float* in_w   = (const float*)d_in[5];
    const float* in_b   = (const float*)d_in[6];
    const float* out_w  = (const float*)d_in[7];
    const float* out_b  = (const float*)d_in[8];
    const float* ic_w1  = (const float*)d_in[9];
    const float* ic_b1  = (const float*)d_in[10];
    const float* ic_w2  = (const float*)d_in[11];
    const float* ic_b2  = (const float*)d_in[12];
    const float* ref_w1 = (const float*)d_in[13];
    const float* ref_b1 = (const float*)d_in[14];
    const float* ref_w2 = (const float*)d_in[15];
    const float* ref_b2 = (const float*)d_in[16];
    const float* wp     = (const float*)d_in[17];
    const float* qp_w   = (const float*)d_in[18];
    const float* qp_b   = (const float*)d_in[19];
    float* out = (float*)d_out;

    float* buf = nullptr;
    cudaGetSymbolAddress((void**)&buf, g_buf);
    float* X    = buf + OFF_X;
    float* QKV  = buf + OFF_QKV;
    float* S    = buf + OFF_S;
    float* O1   = buf + OFF_O1;
    float* AO   = buf + OFF_AO;
    float* K2   = buf + OFF_K2;
    float* BQP  = buf + OFF_BQP;
    float* QB   = buf + OFF_QB;
    float* E    = buf + OFF_E;
    float* VT   = buf + OFF_VT;
    float* RS   = buf + OFF_RS;
    float* HB   = buf + OFF_HB;
    float* Hbuf = buf + OFF_H;
    float* LG   = buf + OFF_LG;
    float* SOFF = buf + OFF_SOFF;
    float* EOFF = buf + OFF_EOFF;
    float* G    = buf + OFF_G;
    float* AL   = buf + OFF_AL;
    float* BE   = buf + OFF_BE;
    float* Avec = buf + OFF_A;
    float* Bvec = buf + OFF_B;
    float* pool = buf + OFF_POOL;
    float* misc = buf + OFF_MISC;

    // x = ne + t*W_time^T + b_time ; zero pooled accumulator
    k_x<<<(SN * SD + 255) / 256, 256>>>(ne, tp, W_time, b_time, X, pool);

    // QKV = X @ in_w^T + in_b
    tgemm<<<dim3(24, 12, 1), 256>>>(SN, 3 * SD, SD, X, SD, 0, in_w, SD, 0,
                                    in_b, QKV, 3 * SD, 0, 1.f, 1, nullptr, 0, 1);
    // S_h = Q_h @ K_h^T / sqrt(DH)
    tgemm<<<dim3(24, 12, SH), 256>>>(SN, SN, SDH, QKV, 3 * SD, SDH,
                                     QKV + SD, 3 * SD, SDH, nullptr,
                                     S, SN, (long)SN * SN, ISQ, 1, nullptr, 0, 1);
    k_rowsoft2<<<SH * SN, 256>>>(S, RS);

    // VT[h][n][k] = V_h^T
    k_vt<<<dim3(SN / 32, SDH / 32, SH), dim3(32, 8)>>>(QKV, VT);

    // pre-init split-K outputs with biases
    k_init5<<<(SN * SD + 255) / 256, 256>>>(O1, AO, K2, BQP, QB, out_b, in_b, qp_b);

    // O1_h = diag(RS_h) * expS_h @ VT_h^T   (split-K 4)
    tgemm<<<dim3(2, 12, SH * 4), 256>>>(SN, SDH, SN, S, SN, (long)SN * SN,
                                        VT, SN, (long)SDH * SN, nullptr,
                                        O1, SD, SDH, 1.f, 4, RS, SN, 1);
    // AO = O1 @ out_w^T + out_b  (split-K 4)
    tgemm<<<dim3(8, 12, 4), 256>>>(SN, SD, SD, O1, SD, 0, out_w, SD, 0,
                                   nullptr, AO, SD, 0, 1.f, 4, nullptr, 0, 1);

    k_pool<<<12, 512>>>(AO, pool);
    k_cls<<<1, 128>>>(pool, ic_w1, ic_b1, ic_w2, ic_b2, out, out_size);
    k_tmm<<<1, 256>>>(tp, misc);

    // K2 = AO @ wk^T + bk  (split-K 4)
    tgemm<<<dim3(8, 12, 4), 256>>>(SN, SD, SD, AO, SD, 0,
                                   in_w + (long)SD * SD, SD, 0, nullptr,
                                   K2, SD, 0, 1.f, 4, nullptr, 0, 1);
    // BQP = AO @ qp_w[:, :512]^T + qp_b  (ldb=514 -> unaligned)
    tgemm<<<dim3(8, 12, 4), 256>>>(SN, SD, SD, AO, SD, 0, qp_w, QPW_LD, 0,
                                   nullptr, BQP, SD, 0, 1.f, 4, nullptr, 0, 0);
    // QB = BQP @ wq^T + bq  (split-K 4)
    tgemm<<<dim3(8, 12, 4), 256>>>(SN, SD, SD, BQP, SD, 0, in_w, SD, 0,
                                   nullptr, QB, SD, 0, 1.f, 4, nullptr, 0, 1);
    // E = exp(QB_h @ K2_h^T / sqrt(DH) - rowmax)
    tgemm<<<dim3(24, 12, SH), 256>>>(SN, SN, SDH, QB, SD, SDH, K2, SD, SDH,
                                     nullptr, E, SN, (long)SN * SN, ISQ, 1,
                                     nullptr, 0, 1);
    k_rowsoft2<<<SH * SN, 256>>>(E, nullptr);

    k_ab<<<1, 512>>>(in_w, qp_w, Avec, Bvec);
    k_alphabeta<<<dim3(6, SH), 256>>>(Avec, Bvec, K2, AL, BE);

    for (int l = 0; l < SNL; l++) {
        // hbase = AO @ ref_w1_l[:, :512]^T + ref_b1_l  (split-K 8, ldb=514)
        k_init<<<(SN * 128 + 255) / 256, 256>>>(ref_b1 + l * 128, HB, 128, SN * 128);
        tgemm<<<dim3(2, 12, 8), 256>>>(SN, 128, SD, AO, SD, 0,
                                       ref_w1 + (long)l * 128 * QPW_LD, QPW_LD, 0,
                                       nullptr, HB, 128, 0, 1.f, 8, nullptr, 0, 0);
        k_hbuf<<<(SNI * SN * 128 + 255) / 256, 256>>>(HB, ref_w1, misc, Hbuf, l);
        // logits = H @ ref_w2_l^T + ref_b2_l  (batched over 5 intervals)
        tgemm<<<dim3(4, 12, SNI), 256>>>(SN, 200, 128, Hbuf, 128, (long)SN * 128,
                                         ref_w2 + (long)l * 200 * 128, 128, 0,
                                         ref_b2 + l * 200, LG, 200, (long)SN * 200,
                                         1.f, 1, nullptr, 0, 1);
        k_soff<<<SNI * SN, 64>>>(LG, wp, SOFF, EOFF);
        k_gprep<<<SH * SNI, 256>>>(AL, BE, SOFF, EOFF, misc, G);
        k_accum<<<dim3(SN / 16, SH), 512>>>(E, G, misc);
        k_update<<<1, 32>>>(misc);
    }

    k_outb<<<1, 32>>>(misc, out, out_size);
}

// round 9
// speedup vs baseline: 3.0229x; 1.0939x over previous
#include <cuda_runtime.h>
#include <cuda_bf16.h>
#include <math.h>

#define SN 1536        // sequence length
#define SD 512         // model dim
#define SH 4           // heads
#define SDH 128        // head dim
#define SNI 5
#define SNL 3
#define QPW_LD 514     // D+2
#define ISQ 0.0883883476483184405f  // 1/sqrt(128)

typedef unsigned int u32;

// ---------------- static scratch ----------------
#define SZ_X    (SN*SD)
#define SZ_QKV  (SN*3*SD)
#define SZ_S    (SH*SN*SN)
#define SZ_O1   (SN*SD)
#define SZ_AO   (SN*SD)
#define SZ_K2   (SN*SD)
#define SZ_BQP  (SN*SD)
#define SZ_QB   (SN*SD)
#define SZ_E    (SH*SN*SN)
#define SZ_VT   (SH*SDH*SN)
#define SZ_RS   (SH*SN)
#define SZ_HB   (SNL*SN*128)
#define SZ_LG   (SNI*SN*200)
#define SZ_SOFF (SNI*SN)
#define SZ_EOFF (SNI*SN)
#define SZ_AL   (SH*SN)
#define SZ_BE   (SH*SN)
#define SZ_A    (SD)
#define SZ_B    (SD)
#define SZ_POOL (SD)
#define SZ_W5   (SNL*128)
#define SZ_W6   (SNL*128)
#define SZ_MISC (32)

#define OFF_X    0
#define OFF_QKV  (OFF_X + SZ_X)
#define OFF_S    (OFF_QKV + SZ_QKV)
#define OFF_O1   (OFF_S + SZ_S)
#define OFF_AO   (OFF_O1 + SZ_O1)
#define OFF_K2   (OFF_AO + SZ_AO)
#define OFF_BQP  (OFF_K2 + SZ_K2)
#define OFF_QB   (OFF_BQP + SZ_BQP)
#define OFF_E    (OFF_QB + SZ_QB)
#define OFF_VT   (OFF_E + SZ_E)
#define OFF_RS   (OFF_VT + SZ_VT)
#define OFF_HB   (OFF_RS + SZ_RS)
#define OFF_LG   (OFF_HB + SZ_HB)
#define OFF_SOFF (OFF_LG + SZ_LG)
#define OFF_EOFF (OFF_SOFF + SZ_SOFF)
#define OFF_AL   (OFF_EOFF + SZ_EOFF)
#define OFF_BE   (OFF_AL + SZ_AL)
#define OFF_A    (OFF_BE + SZ_BE)
#define OFF_B    (OFF_A + SZ_A)
#define OFF_POOL (OFF_B + SZ_B)
#define OFF_W5   (OFF_POOL + SZ_POOL)
#define OFF_W6   (OFF_W5 + SZ_W5)
#define OFF_MISC (OFF_W6 + SZ_W6)
#define BUF_TOTAL (OFF_MISC + SZ_MISC)

__device__ float g_buf[BUF_TOTAL];

// misc: 0 tmin, 1 tmax, [2..6] start, [7..11] end, [12..16] ds, [17..21] de

// ---------------- MMA helpers ----------------
__device__ __forceinline__ u32 smem_u32(const void* p) {
    u32 a;
    asm("{ .reg .u64 t; cvta.to.shared.u64 t, %1; cvt.u32.u64 %0, t; }" : "=r"(a) : "l"(p));
    return a;
}
__device__ __forceinline__ void ldsm4(u32* r, u32 addr) {
    asm volatile("ldmatrix.sync.aligned.m8n8.x4.shared.b16 {%0,%1,%2,%3}, [%4];"
                 : "=r"(r[0]), "=r"(r[1]), "=r"(r[2]), "=r"(r[3]) : "r"(addr));
}
__device__ __forceinline__ void mma16816(float* c, const u32* a, const u32* b) {
    asm volatile(
        "mma.sync.aligned.m16n8k16.row.col.f32.bf16.bf16.f32 "
        "{%0,%1,%2,%3}, {%4,%5,%6,%7}, {%8,%9}, {%0,%1,%2,%3};"
        : "+f"(c[0]), "+f"(c[1]), "+f"(c[2]), "+f"(c[3])
        : "r"(a[0]), "r"(a[1]), "r"(a[2]), "r"(a[3]), "r"(b[0]), "r"(b[1]));
}
__device__ __forceinline__ void split4(float4 v, uint2& hi, uint2& lo) {
    __nv_bfloat16 h0 = __float2bfloat16_rn(v.x), h1 = __float2bfloat16_rn(v.y),
                  h2 = __float2bfloat16_rn(v.z), h3 = __float2bfloat16_rn(v.w);
    __nv_bfloat162 hp0 = __halves2bfloat162(h0, h1), hp1 = __halves2bfloat162(h2, h3);
    __nv_bfloat162 lp0 = __floats2bfloat162_rn(v.x - __bfloat162float(h0),
                                               v.y - __bfloat162float(h1));
    __nv_bfloat162 lp1 = __floats2bfloat162_rn(v.z - __bfloat162float(h2),
                                               v.w - __bfloat162float(h3));
    hi = make_uint2(*(u32*)&hp0, *(u32*)&hp1);
    lo = make_uint2(*(u32*)&lp0, *(u32*)&lp1);
}

// ---------------- tensor-core NT GEMM (HMMA bf16, 3-term split) ----------------
// MODE 0: plain (bias if ksplit==1, else atomic into pre-init C)
// MODE 1: C = exp(scale*acc); if rsbuf, atomic row-sums into rsbuf (ksplit==1)
// MODE 2: C += (scale / rsbuf[r]) * acc  (split-K atomic)
// MODE 3: A-load transform relu(A + s*hb512 + e*hb513), bias store (ksplit==1)
#define LDT 40
template<int MODE>
__device__ __forceinline__ float4 ldA4(const float* p, int kcol,
                                       const float* hb5, const float* hb6,
                                       float s, float e) {
    float4 v = *(const float4*)p;
    if (MODE == 3) {
        float4 w5 = *(const float4*)(hb5 + kcol);
        float4 w6 = *(const float4*)(hb6 + kcol);
        v.x = fmaxf(v.x + s * w5.x + e * w6.x, 0.f);
        v.y = fmaxf(v.y + s * w5.y + e * w6.y, 0.f);
        v.z = fmaxf(v.z + s * w5.z + e * w6.z, 0.f);
        v.w = fmaxf(v.w + s * w5.w + e * w6.w, 0.f);
    }
    return v;
}

template<int MODE>
__global__ void __launch_bounds__(256)
tgemm(int M, int N, int K,
      const float* __restrict__ A, int lda, long sA,
      const float* __restrict__ B, int ldb, long sB,
      const float* __restrict__ bias,
      float* __restrict__ C, int ldc, long sC,
      float scale, int ksplit,
      float* __restrict__ rsbuf, long sRS, int alignB,
      const float* __restrict__ hb5, const float* __restrict__ hb6,
      const float* __restrict__ misc) {
    __shared__ __nv_bfloat16 sA_[2][128 * LDT];
    __shared__ __nv_bfloat16 sB_[2][64 * LDT];

    int batch = blockIdx.z / ksplit;
    int kz = blockIdx.z % ksplit;
    int Kc = K / ksplit;
    int kbeg = kz * Kc;
    A += (long)batch * sA;
    B += (long)batch * sB;
    C += (long)batch * sC;
    int brow = blockIdx.y * 128, bcol = blockIdx.x * 64;

    float hs = 0.f, he = 0.f;
    if (MODE == 3) { hs = misc[2 + batch]; he = misc[7 + batch]; }

    int tid = threadIdx.x;
    int wid = tid >> 5, lane = tid & 31;
    int wm = (wid & 3) * 32;
    int wn = (wid >> 2) * 32;

    u32 aBase[2] = { smem_u32(sA_[0]), smem_u32(sA_[1]) };
    u32 bBase[2] = { smem_u32(sB_[0]), smem_u32(sB_[1]) };

    int rowsel = (lane & 7) + ((lane >> 3) & 1) * 8;
    int ksel = (lane >> 4) * 8;

    float acc[2][4][4];
#pragma unroll
    for (int mi = 0; mi < 2; mi++)
#pragma unroll
        for (int ni = 0; ni < 4; ni++)
#pragma unroll
            for (int j = 0; j < 4; j++) acc[mi][ni][j] = 0.f;

    float4 pa[4], pb[2];
#pragma unroll
    for (int i = 0; i < 4; i++) {
        int idx = tid + i * 256;
        int row = idx >> 3, col = (idx & 7) * 4;
        pa[i] = ldA4<MODE>(A + (long)(brow + row) * lda + kbeg + col, kbeg + col, hb5, hb6, hs, he);
    }
#pragma unroll
    for (int i = 0; i < 2; i++) {
        int idx = tid + i * 256;
        int row = idx >> 3, col = (idx & 7) * 4;
        int rB = bcol + row;
        if (rB < N) {
            const float* bp = B + (long)rB * ldb + kbeg + col;
            pb[i] = alignB ? *(const float4*)bp
                           : make_float4(bp[0], bp[1], bp[2], bp[3]);
        } else pb[i] = make_float4(0.f, 0.f, 0.f, 0.f);
    }

    for (int kc = 0; kc < Kc; kc += 32) {
#pragma unroll
        for (int i = 0; i < 4; i++) {
            int idx = tid + i * 256;
            int row = idx >> 3, col = (idx & 7) * 4;
            uint2 hi, lo;
            split4(pa[i], hi, lo);
            *(uint2*)&sA_[0][row * LDT + col] = hi;
            *(uint2*)&sA_[1][row * LDT + col] = lo;
        }
#pragma unroll
        for (int i = 0; i < 2; i++) {
            int idx = tid + i * 256;
            int row = idx >> 3, col = (idx & 7) * 4;
            uint2 hi, lo;
            split4(pb[i], hi, lo);
            *(uint2*)&sB_[0][row * LDT + col] = hi;
            *(uint2*)&sB_[1][row * LDT + col] = lo;
        }
        __syncthreads();

        int kn = kbeg + kc + 32;
        if (kc + 32 < Kc) {
#pragma unroll
            for (int i = 0; i < 4; i++) {
                int idx = tid + i * 256;
                int row = idx >> 3, col = (idx & 7) * 4;
                pa[i] = ldA4<MODE>(A + (long)(brow + row) * lda + kn + col, kn + col, hb5, hb6, hs, he);
            }
#pragma unroll
            for (int i = 0; i < 2; i++) {
                int idx = tid + i * 256;
                int row = idx >> 3, col = (idx & 7) * 4;
                int rB = bcol + row;
                if (rB < N) {
                    const float* bp = B + (long)rB * ldb + kn + col;
                    pb[i] = alignB ? *(const float4*)bp
                                   : make_float4(bp[0], bp[1], bp[2], bp[3]);
                } else pb[i] = make_float4(0.f, 0.f, 0.f, 0.f);
            }
        }

#pragma unroll
        for (int ks = 0; ks < 32; ks += 16) {
            u32 ahi[2][4], alo[2][4], bhi[4][2], blo[4][2];
#pragma unroll
            for (int mi = 0; mi < 2; mi++) {
                u32 off = ((wm + mi * 16 + rowsel) * LDT + ks + ksel) * 2;
                ldsm4(ahi[mi], aBase[0] + off);
                ldsm4(alo[mi], aBase[1] + off);
            }
#pragma unroll
            for (int nj = 0; nj < 2; nj++) {
                u32 off = ((wn + nj * 16 + rowsel) * LDT + ks + ksel) * 2;
                u32 t0[4], t1[4];
                ldsm4(t0, bBase[0] + off);
                ldsm4(t1, bBase[1] + off);
                bhi[2 * nj][0] = t0[0]; bhi[2 * nj][1] = t0[2];
                bhi[2 * nj + 1][0] = t0[1]; bhi[2 * nj + 1][1] = t0[3];
                blo[2 * nj][0] = t1[0]; blo[2 * nj][1] = t1[2];
                blo[2 * nj + 1][0] = t1[1]; blo[2 * nj + 1][1] = t1[3];
            }
#pragma unroll
            for (int mi = 0; mi < 2; mi++)
#pragma unroll
                for (int ni = 0; ni < 4; ni++) {
                    mma16816(acc[mi][ni], ahi[mi], bhi[ni]);
                    mma16816(acc[mi][ni], ahi[mi], blo[ni]);
                    mma16816(acc[mi][ni], alo[mi], bhi[ni]);
                }
        }
        __syncthreads();
    }

    // epilogue
    int g = lane >> 2, t = lane & 3;
#pragma unroll
    for (int mi = 0; mi < 2; mi++) {
        int r0 = brow + wm + mi * 16 + g;
        int r1 = r0 + 8;
        float s0 = scale, s1 = scale;
        if (MODE == 2) {
            s0 = scale / rsbuf[sRS * batch + r0];
            s1 = scale / rsbuf[sRS * batch + r1];
        }
        float sum0 = 0.f, sum1 = 0.f;
#pragma unroll
        for (int ni = 0; ni < 4; ni++) {
            int cc = bcol + wn + ni * 8 + 2 * t;
            float v00 = acc[mi][ni][0] * s0, v01 = acc[mi][ni][1] * s0;
            float v10 = acc[mi][ni][2] * s1, v11 = acc[mi][ni][3] * s1;
            if (MODE == 1) {
                v00 = __expf(v00); v01 = __expf(v01);
                v10 = __expf(v10); v11 = __expf(v11);
                sum0 += v00 + v01; sum1 += v10 + v11;
                if (cc < N) { C[(long)r0 * ldc + cc] = v00; C[(long)r1 * ldc + cc] = v10; }
                if (cc + 1 < N) { C[(long)r0 * ldc + cc + 1] = v01; C[(long)r1 * ldc + cc + 1] = v11; }
            } else if (MODE == 2 || ksplit > 1) {
                if (cc < N) {
                    atomicAdd(&C[(long)r0 * ldc + cc], v00);
                    atomicAdd(&C[(long)r1 * ldc + cc], v10);
                }
                if (cc + 1 < N) {
                    atomicAdd(&C[(long)r0 * ldc + cc + 1], v01);
                    atomicAdd(&C[(long)r1 * ldc + cc + 1], v11);
                }
            } else {
                if (bias) {
                    if (cc < N) { v00 += bias[cc]; v10 += bias[cc]; }
                    if (cc + 1 < N) { v01 += bias[cc + 1]; v11 += bias[cc + 1]; }
                }
                if (cc < N) { C[(long)r0 * ldc + cc] = v00; C[(long)r1 * ldc + cc] = v10; }
                if (cc + 1 < N) { C[(long)r0 * ldc + cc + 1] = v01; C[(long)r1 * ldc + cc + 1] = v11; }
            }
        }
        if (MODE == 1 && rsbuf) {
            sum0 += __shfl_xor_sync(0xffffffffu, sum0, 1);
            sum0 += __shfl_xor_sync(0xffffffffu, sum0, 2);
            sum1 += __shfl_xor_sync(0xffffffffu, sum1, 1);
            sum1 += __shfl_xor_sync(0xffffffffu, sum1, 2);
            if (t == 0) {
                atomicAdd(&rsbuf[sRS * batch + r0], sum0);
                atomicAdd(&rsbuf[sRS * batch + r1], sum1);
            }
        }
    }
}

// ---------------- small kernels ----------------

__global__ void k_x(const float* __restrict__ ne, const float* __restrict__ tp,
                    const float* __restrict__ wt, const float* __restrict__ bt,
                    float* __restrict__ X, float* __restrict__ pool,
                    float* __restrict__ RS) {
    int idx = blockIdx.x * 256 + threadIdx.x;
    if (idx < SN * SD) {
        int i = idx >> 9, d = idx & 511;
        X[idx] = ne[idx] + tp[i] * wt[d] + bt[d];
    }
    if (idx < SD) pool[idx] = 0.f;
    if (idx < SH * SN) RS[idx] = 0.f;
}

__global__ void k_init5(float* __restrict__ O1, float* __restrict__ AO,
                        float* __restrict__ K2, float* __restrict__ BQP,
                        float* __restrict__ QB,
                        const float* __restrict__ out_b, const float* __restrict__ in_b,
                        const float* __restrict__ qp_b) {
    int idx = blockIdx.x * 256 + threadIdx.x;
    if (idx < SN * SD) {
        int c = idx & 511;
        O1[idx] = 0.f;
        AO[idx] = out_b[c];
        K2[idx] = in_b[SD + c];
        BQP[idx] = qp_b[c];
        QB[idx] = in_b[c];
    }
}

// init HB (3 layers, per-layer bias) + extract w1 s/e columns
__global__ void k_initHB(const float* __restrict__ ref_b1, const float* __restrict__ ref_w1,
                         float* __restrict__ HB, float* __restrict__ w5,
                         float* __restrict__ w6) {
    int idx = blockIdx.x * 256 + threadIdx.x;
    if (idx < SNL * SN * 128) {
        int l = idx / (SN * 128);
        int c = idx & 127;
        HB[idx] = ref_b1[l * 128 + c];
    }
    if (idx < SNL * 128) {
        w5[idx] = ref_w1[(long)idx * QPW_LD + 512];
        w6[idx] = ref_w1[(long)idx * QPW_LD + 513];
    }
}

// V transpose: VT[h][n][k] = QKV[k][2*SD + h*128 + n]
__global__ void k_vt(const float* __restrict__ QKV, float* __restrict__ VT) {
    __shared__ float t[32][33];
    int h = blockIdx.z;
    int k0 = blockIdx.x * 32, n0 = blockIdx.y * 32;
    int x = threadIdx.x, y0 = threadIdx.y;
#pragma unroll
    for (int dy = 0; dy < 32; dy += 8) {
        int k = k0 + y0 + dy;
        t[y0 + dy][x] = QKV[(long)k * (3 * SD) + 2 * SD + h * SDH + n0 + x];
    }
    __syncthreads();
#pragma unroll
    for (int dy = 0; dy < 32; dy += 8) {
        int n = n0 + y0 + dy;
        VT[((long)h * SDH + n) * SN + k0 + x] = t[x][y0 + dy];
    }
}

__global__ void k_pool(const float* __restrict__ AO, float* __restrict__ pool) {
    int d = threadIdx.x;  // 512
    int r0 = blockIdx.x * 128;
    float s = 0.f;
    for (int r = 0; r < 128; r++) s += AO[(long)(r0 + r) * SD + d];
    atomicAdd(&pool[d], s);
}

__global__ void k_cls(const float* __restrict__ pool,
                      const float* __restrict__ w1, const float* __restrict__ b1,
                      const float* __restrict__ w2, const float* __restrict__ b2,
                      float* __restrict__ out, int out_size) {
    __shared__ float pv[SD];
    __shared__ float h1[128];
    __shared__ float lg[5];
    int tid = threadIdx.x;  // 128
    for (int i = tid; i < SD; i += 128) pv[i] = pool[i] * (1.f / SN);
    __syncthreads();
    {
        float r = b1[tid];
        const float* wr = w1 + (long)tid * SD;
        for (int d = 0; d < SD; d++) r += wr[d] * pv[d];
        h1[tid] = fmaxf(r, 0.f);
    }
    __syncthreads();
    if (tid < 5) {
        float r = b2[tid];
        const float* wr = w2 + (long)tid * 128;
        for (int j = 0; j < 128; j++) r += wr[j] * h1[j];
        lg[tid] = r;
    }
    __syncthreads();
    if (tid == 0) {
        int arg = 0;
        float best = lg[0];
        for (int i = 1; i < 5; i++)
            if (lg[i] > best) { best = lg[i]; arg = i; }
        int num = arg + 1;
        if (out_size >= 15)
            for (int i = 0; i < 5; i++) out[10 + i] = (i < num) ? 1.f : 0.f;
    }
}

__global__ void k_tmm(const float* __restrict__ tp, float* __restrict__ misc) {
    __shared__ float mn[256], mx[256];
    int tid = threadIdx.x;
    float a = 1e30f, b = -1e30f;
    for (int i = tid; i < SN; i += 256) {
        float v = tp[i];
        a = fminf(a, v);
        b = fmaxf(b, v);
    }
    mn[tid] = a; mx[tid] = b;
    __syncthreads();
    for (int s = 128; s > 0; s >>= 1) {
        if (tid < s) {
            mn[tid] = fminf(mn[tid], mn[tid + s]);
            mx[tid] = fmaxf(mx[tid], mx[tid + s]);
        }
        __syncthreads();
    }
    if (tid == 0) {
        float tmin = mn[0], tmax = mx[0];
        misc[0] = tmin; misc[1] = tmax;
        float step = (tmax - tmin) / 5.f;
        for (int i = 0; i < 5; i++) {
            misc[2 + i] = tmin + i * step;
            misc[7 + i] = tmin + (i + 1) * step;
        }
    }
    if (tid >= 32 && tid < 42) misc[12 + (tid - 32)] = 0.f;  // zero ds/de
}

__global__ void k_ab(const float* __restrict__ in_w, const float* __restrict__ qp_w,
                     float* __restrict__ a, float* __restrict__ b) {
    __shared__ float u[SD], v[SD];
    int tid = threadIdx.x;  // 512
    u[tid] = qp_w[(long)tid * QPW_LD + 512];
    v[tid] = qp_w[(long)tid * QPW_LD + 513];
    __syncthreads();
    float sa = 0.f, sb = 0.f;
    const float* wr = in_w + (long)tid * SD;
    for (int d = 0; d < SD; d++) {
        float w = wr[d];
        sa += w * u[d];
        sb += w * v[d];
    }
    a[tid] = sa; b[tid] = sb;
}

__global__ void k_alphabeta(const float* __restrict__ a, const float* __restrict__ b,
                            const float* __restrict__ K2,
                            float* __restrict__ alpha, float* __restrict__ beta) {
    int h = blockIdx.y;
    int k = blockIdx.x * 256 + threadIdx.x;
    __shared__ float a_s[SDH], b_s[SDH];
    if (threadIdx.x < SDH) {
        a_s[threadIdx.x] = a[h * SDH + threadIdx.x];
        b_s[threadIdx.x] = b[h * SDH + threadIdx.x];
    }
    __syncthreads();
    if (k >= SN) return;
    const float* kr = K2 + (long)k * SD + h * SDH;
    float sa = 0.f, sb = 0.f;
    for (int j = 0; j < SDH; j++) {
        float kv = kr[j];
        sa += kv * a_s[j];
        sb += kv * b_s[j];
    }
    alpha[h * SN + k] = sa * ISQ;
    beta[h * SN + k] = sb * ISQ;
}

__global__ void k_soff(const float* __restrict__ LG, const float* __restrict__ wp,
                       float* __restrict__ SOFF, float* __restrict__ EOFF) {
    int r = blockIdx.x;
    int warp = threadIdx.x >> 5, lane = threadIdx.x & 31;
    const float* row = LG + (long)r * 200 + warp * 100;
    float m = -1e30f;
    for (int k = lane; k < 100; k += 32) m = fmaxf(m, row[k]);
    for (int o = 16; o > 0; o >>= 1) m = fmaxf(m, __shfl_xor_sync(0xffffffffu, m, o));
    float s = 0.f, d = 0.f;
    for (int k = lane; k < 100; k += 32) {
        float e = __expf(row[k] - m);
        s += e;
        d += e * wp[k];
    }
    for (int o = 16; o > 0; o >>= 1) {
        s += __shfl_xor_sync(0xffffffffu, s, o);
        d += __shfl_xor_sync(0xffffffffu, d, o);
    }
    if (lane == 0) {
        float val = d / s;
        if (warp == 0) SOFF[r] = val; else EOFF[r] = val;
    }
}

// fused gprep + accum: build G tiles on the fly, one pass over E
__global__ void k_accum2(const float* __restrict__ E,
                         const float* __restrict__ AL, const float* __restrict__ BE,
                         const float* __restrict__ SOFF, const float* __restrict__ EOFF,
                         float* __restrict__ misc) {
    int h = blockIdx.y;
    int warp = threadIdx.x >> 5, lane = threadIdx.x & 31;
    int q = blockIdx.x * 16 + warp;
    __shared__ float Gs[15][256];
    __shared__ float se[10];
    if (threadIdx.x < 10) se[threadIdx.x] = misc[2 + threadIdx.x];
    const float* Erow = E + (long)h * SN * SN + (long)q * SN;
    float acc[15];
#pragma unroll
    for (int c = 0; c < 15; c++) acc[c] = 0.f;
    for (int k0 = 0; k0 < SN; k0 += 256) {
        __syncthreads();
        for (int idx = threadIdx.x; idx < 5 * 256; idx += 512) {
            int i = idx >> 8, kk = idx & 255;
            int k = k0 + kk;
            float al = AL[h * SN + k], be = BE[h * SN + k];
            float g = __expf(se[i] * al + se[5 + i] * be);
            Gs[3 * i][kk] = g;
            Gs[3 * i + 1][kk] = g * SOFF[i * SN + k];
            Gs[3 * i + 2][kk] = g * EOFF[i * SN + k];
        }
        __syncthreads();
#pragma unroll
        for (int s = 0; s < 8; s++) {
            int kk = lane + 32 * s;
            float ev = Erow[k0 + kk];
#pragma unroll
            for (int c = 0; c < 15; c++) acc[c] += ev * Gs[c][kk];
        }
    }
#pragma unroll
    for (int c = 0; c < 15; c++)
        for (int o = 16; o > 0; o >>= 1)
            acc[c] += __shfl_xor_sync(0xffffffffu, acc[c], o);
    if (lane == 0) {
#pragma unroll
        for (int i = 0; i < 5; i++) {
            float inv = 0.25f / acc[3 * i];
            atomicAdd(&misc[12 + i], acc[3 * i + 1] * inv);
            atomicAdd(&misc[17 + i], acc[3 * i + 2] * inv);
        }
    }
}

__global__ void k_update(float* __restrict__ misc) {
    int t = threadIdx.x;
    if (t < 5) {
        misc[2 + t] += misc[12 + t];
        misc[7 + t] += misc[17 + t];
        misc[12 + t] = 0.f;
        misc[17 + t] = 0.f;
    }
}

__global__ void k_outb(const float* __restrict__ misc, float* __restrict__ out, int out_size) {
    int t = threadIdx.x;
    if (t < 5 && out_size >= 10) {
        out[2 * t] = misc[2 + t];
        out[2 * t + 1] = misc[7 + t];
    }
}

// ---------------- host ----------------
extern "C" void kernel_launch(void* const* d_in, const int* in_sizes, int n_in,
                              void* d_out, int out_size) {
    const float* ne     = (const float*)d_in[0];
    const float* tp     = (const float*)d_in[1];
    const float* W_time = (const float*)d_in[3];
    const float* b_time = (const float*)d_in[4];
    const float* in_w   = (const float*)d_in[5];
    const float* in_b   = (const float*)d_in[6];
    const float* out_w  = (const float*)d_in[7];
    const float* out_b  = (const float*)d_in[8];
    const float* ic_w1  = (const float*)d_in[9];
    const float* ic_b1  = (const float*)d_in[10];
    const float* ic_w2  = (const float*)d_in[11];
    const float* ic_b2  = (const float*)d_in[12];
    const float* ref_w1 = (const float*)d_in[13];
    const float* ref_b1 = (const float*)d_in[14];
    const float* ref_w2 = (const float*)d_in[15];
    const float* ref_b2 = (const float*)d_in[16];
    const float* wp     = (const float*)d_in[17];
    const float* qp_w   = (const float*)d_in[18];
    const float* qp_b   = (const float*)d_in[19];
    float* out = (float*)d_out;

    float* buf = nullptr;
    cudaGetSymbolAddress((void**)&buf, g_buf);
    float* X    = buf + OFF_X;
    float* QKV  = buf + OFF_QKV;
    float* S    = buf + OFF_S;
    float* O1   = buf + OFF_O1;
    float* AO   = buf + OFF_AO;
    float* K2   = buf + OFF_K2;
    float* BQP  = buf + OFF_BQP;
    float* QB   = buf + OFF_QB;
    float* E    = buf + OFF_E;
    float* VT   = buf + OFF_VT;
    float* RS   = buf + OFF_RS;
    float* HB   = buf + OFF_HB;
    float* LG   = buf + OFF_LG;
    float* SOFF = buf + OFF_SOFF;
    float* EOFF = buf + OFF_EOFF;
    float* AL   = buf + OFF_AL;
    float* BEp  = buf + OFF_BE;
    float* Avec = buf + OFF_A;
    float* Bvec = buf + OFF_B;
    float* pool = buf + OFF_POOL;
    float* W5   = buf + OFF_W5;
    float* W6   = buf + OFF_W6;
    float* misc = buf + OFF_MISC;

    // X = ne + t*Wt^T + bt ; zero pool + RS
    k_x<<<(SN * SD + 255) / 256, 256>>>(ne, tp, W_time, b_time, X, pool, RS);

    // QKV = X @ in_w^T + in_b
    tgemm<0><<<dim3(24, 12, 1), 256>>>(SN, 3 * SD, SD, X, SD, 0, in_w, SD, 0,
                                       in_b, QKV, 3 * SD, 0, 1.f, 1,
                                       nullptr, 0, 1, nullptr, nullptr, nullptr);
    // S_h = exp(Q_h @ K_h^T / sqrt(DH)); row-sums into RS
    tgemm<1><<<dim3(24, 12, SH), 256>>>(SN, SN, SDH, QKV, 3 * SD, SDH,
                                        QKV + SD, 3 * SD, SDH, nullptr,
                                        S, SN, (long)SN * SN, ISQ, 1,
                                        RS, SN, 1, nullptr, nullptr, nullptr);
    // VT, pre-init split-K targets
    k_vt<<<dim3(SN / 32, SDH / 32, SH), dim3(32, 8)>>>(QKV, VT);
    k_init5<<<(SN * SD + 255) / 256, 256>>>(O1, AO, K2, BQP, QB, out_b, in_b, qp_b);

    // O1_h = (1/RS_h[r]) * S_h @ VT_h^T  (split-K 4)
    tgemm<2><<<dim3(2, 12, SH * 4), 256>>>(SN, SDH, SN, S, SN, (long)SN * SN,
                                           VT, SN, (long)SDH * SN, nullptr,
                                           O1, SD, SDH, 1.f, 4,
                                           RS, SN, 1, nullptr, nullptr, nullptr);
    // AO = O1 @ out_w^T + out_b  (split-K 4)
    tgemm<0><<<dim3(8, 12, 4), 256>>>(SN, SD, SD, O1, SD, 0, out_w, SD, 0,
                                      nullptr, AO, SD, 0, 1.f, 4,
                                      nullptr, 0, 1, nullptr, nullptr, nullptr);

    k_pool<<<12, 512>>>(AO, pool);
    k_cls<<<1, 128>>>(pool, ic_w1, ic_b1, ic_w2, ic_b2, out, out_size);
    k_tmm<<<1, 256>>>(tp, misc);

    // K2 = AO @ wk^T + bk
    tgemm<0><<<dim3(8, 12, 4), 256>>>(SN, SD, SD, AO, SD, 0,
                                      in_w + (long)SD * SD, SD, 0, nullptr,
                                      K2, SD, 0, 1.f, 4,
                                      nullptr, 0, 1, nullptr, nullptr, nullptr);
    // BQP = AO @ qp_w[:, :512]^T + qp_b  (ldb=514 unaligned)
    tgemm<0><<<dim3(8, 12, 4), 256>>>(SN, SD, SD, AO, SD, 0, qp_w, QPW_LD, 0,
                                      nullptr, BQP, SD, 0, 1.f, 4,
                                      nullptr, 0, 0, nullptr, nullptr, nullptr);
    // QB = BQP @ wq^T + bq
    tgemm<0><<<dim3(8, 12, 4), 256>>>(SN, SD, SD, BQP, SD, 0, in_w, SD, 0,
                                      nullptr, QB, SD, 0, 1.f, 4,
                                      nullptr, 0, 1, nullptr, nullptr, nullptr);
    // E = exp(QB_h @ K2_h^T / sqrt(DH))
    tgemm<1><<<dim3(24, 12, SH), 256>>>(SN, SN, SDH, QB, SD, SDH, K2, SD, SDH,
                                        nullptr, E, SN, (long)SN * SN, ISQ, 1,
                                        nullptr, 0, 1, nullptr, nullptr, nullptr);

    k_ab<<<1, 512>>>(in_w, qp_w, Avec, Bvec);
    k_alphabeta<<<dim3(6, SH), 256>>>(Avec, Bvec, K2, AL, BEp);

    // HB for all 3 layers (batched, split-K 8) + w1 s/e tables
    k_initHB<<<(SNL * SN * 128 + 255) / 256, 256>>>(ref_b1, ref_w1, HB, W5, W6);
    tgemm<0><<<dim3(2, 12, SNL * 8), 256>>>(SN, 128, SD, AO, SD, 0,
                                            ref_w1, QPW_LD, (long)128 * QPW_LD,
                                            nullptr, HB, 128, (long)SN * 128, 1.f, 8,
                                            nullptr, 0, 0, nullptr, nullptr, nullptr);

    for (int l = 0; l < SNL; l++) {
        // logits = relu(HB_l + s*w5 + e*w6) @ ref_w2_l^T + ref_b2_l  (batched over 5 intervals)
        tgemm<3><<<dim3(4, 12, SNI), 256>>>(SN, 200, 128, HB + (long)l * SN * 128, 128, 0,
                                            ref_w2 + (long)l * 200 * 128, 128, 0,
                                            ref_b2 + l * 200, LG, 200, (long)SN * 200,
                                            1.f, 1, nullptr, 0, 1,
                                            W5 + l * 128, W6 + l * 128, misc);
        k_soff<<<SNI * SN, 64>>>(LG, wp, SOFF, EOFF);
        k_accum2<<<dim3(SN / 16, SH), 512>>>(E, AL, BEp, SOFF, EOFF, misc);
        k_update<<<1, 32>>>(misc);
    }

    k_outb<<<1, 32>>>(misc, out, out_size);
}